// round 8
// baseline (speedup 1.0000x reference)
#include <cuda_runtime.h>
#include <cstdint>
#include <math.h>

#define BATCH 2
#define NT    2048
#define NSEG1 1536
#define NSEG2 512
#define DM    1024
#define NH    16
#define HD    64

typedef unsigned long long u64;
typedef unsigned int u32;

// Scratch (static device arrays — no allocation)
static __device__ float g_qkv[BATCH * NT * 3 * DM];   // (b, n, 3*1024)
static __device__ float g_q[BATCH * NH * NT * HD];    // (b, h, n, d)
static __device__ float g_k[BATCH * NH * NT * HD];
static __device__ float g_v[BATCH * NH * NT * HD];
static __device__ float g_x[BATCH * NT * DM];         // attention out, (b, n, h*d)

// ---------------------------------------------------------------------------
// Packed fp32 helpers (Blackwell fma.rn.f32x2 — ptxas never auto-fuses)
// ---------------------------------------------------------------------------
__device__ __forceinline__ u64 ffma2(u64 a, u64 b, u64 c) {
    u64 d;
    asm("fma.rn.f32x2 %0, %1, %2, %3;" : "=l"(d) : "l"(a), "l"(b), "l"(c));
    return d;
}
__device__ __forceinline__ u64 fmul2(u64 a, u64 b) {
    u64 d;
    asm("mul.rn.f32x2 %0, %1, %2;" : "=l"(d) : "l"(a), "l"(b));
    return d;
}
__device__ __forceinline__ u64 bcast2(float x) {
    u64 r;
    asm("mov.b64 %0, {%1, %1};" : "=l"(r) : "f"(x));
    return r;
}
__device__ __forceinline__ float2 unpack2(u64 v) {
    float2 f;
    asm("mov.b64 {%0, %1}, %2;" : "=f"(f.x), "=f"(f.y) : "l"(v));
    return f;
}

// cp.async helpers
__device__ __forceinline__ void cp16(u32 saddr, const void* gptr) {
    asm volatile("cp.async.ca.shared.global [%0], [%1], 16;" :: "r"(saddr), "l"(gptr));
}
__device__ __forceinline__ void cp_commit() { asm volatile("cp.async.commit_group;"); }
__device__ __forceinline__ void cp_wait1() { asm volatile("cp.async.wait_group 1;"); }
__device__ __forceinline__ void cp_wait0() { asm volatile("cp.async.wait_group 0;"); }

// ---------------------------------------------------------------------------
// Fast exp on the FMA pipe (avoids MUFU rt=8 bottleneck); valid x <= 0
// ---------------------------------------------------------------------------
__device__ __forceinline__ float fexp(float x) {
    x = fmaxf(x, -80.0f);
    float t = x * 1.4426950408889634f;
    float n = rintf(t);
    float f = t - n;
    float z = f * 0.6931471805599453f;
    float p = 1.0f + z * (1.0f + z * (0.5f + z * (0.16666667f + z * (0.041666667f + z * 0.008333334f))));
    int ni = (int)n;
    float s = __int_as_float((ni + 127) << 23);
    return p * s;
}

// ---------------------------------------------------------------------------
// NT GEMM (round-5 known-good): C[m, n] = sum_k A[m, k] * B[n, k] + bias[n]
// 128x128x16 tiles, 256 threads, 8x8 micro (split-4 rows/cols), packed
// FFMA2 along columns, scalar-bcast rows. Double-buffered smem, 1 sync/chunk.
// ---------------------------------------------------------------------------
__global__ void __launch_bounds__(256, 2)
gemm_nt(const float* __restrict__ A, const float* __restrict__ B,
        const float* __restrict__ bias, float* __restrict__ C,
        int N, int K,
        int aRPB, long long aBS,      // A rows-per-batch, batch stride (elems)
        int cRPB, long long cBS)      // C rows-per-batch, batch stride (elems)
{
    __shared__ float As[2][16][128];
    __shared__ float Bs[2][16][128];

    const int tid = threadIdx.x;
    const int tx = tid & 15;        // col groups {4tx, 64+4tx}
    const int ty = tid >> 4;        // row groups {4ty, 64+4ty}
    const int m0 = blockIdx.y * 128;
    const int n0 = blockIdx.x * 128;

    const int lr = tid >> 1;          // 0..127
    const int lg = (tid & 1) * 2;     // float4-group 0 or 2

    const int am = m0 + lr;
    const int ab = am / aRPB;
    const float* Arow = A + (long long)ab * aBS + (long long)(am - ab * aRPB) * K;
    const float* Brow = B + (long long)(n0 + lr) * K;

    u64 acc[8][4];
#pragma unroll
    for (int i = 0; i < 8; i++)
#pragma unroll
        for (int j = 0; j < 4; j++) acc[i][j] = 0ull;

    // preload chunk 0 into regs, store to buf 0
    float4 a0 = *(const float4*)(Arow + 4 * lg);
    float4 a1 = *(const float4*)(Arow + 4 * lg + 4);
    float4 b0 = *(const float4*)(Brow + 4 * lg);
    float4 b1 = *(const float4*)(Brow + 4 * lg + 4);
    {
        float av[8] = {a0.x, a0.y, a0.z, a0.w, a1.x, a1.y, a1.z, a1.w};
        float bv[8] = {b0.x, b0.y, b0.z, b0.w, b1.x, b1.y, b1.z, b1.w};
#pragma unroll
        for (int t = 0; t < 8; t++) {
            As[0][4 * lg + t][lr] = av[t];
            Bs[0][4 * lg + t][lr] = bv[t];
        }
    }
    __syncthreads();

    const int nIter = K / 16;
    int s = 0;
    for (int it = 0; it < nIter; ++it) {
        if (it + 1 < nIter) {
            int k0n = (it + 1) * 16;
            a0 = *(const float4*)(Arow + k0n + 4 * lg);
            a1 = *(const float4*)(Arow + k0n + 4 * lg + 4);
            b0 = *(const float4*)(Brow + k0n + 4 * lg);
            b1 = *(const float4*)(Brow + k0n + 4 * lg + 4);
        }

#pragma unroll
        for (int kk = 0; kk < 16; kk++) {
            float4 av0 = *(const float4*)&As[s][kk][4 * ty];
            float4 av1 = *(const float4*)&As[s][kk][64 + 4 * ty];
            ulonglong2 bv0 = *(const ulonglong2*)&Bs[s][kk][4 * tx];
            ulonglong2 bv1 = *(const ulonglong2*)&Bs[s][kk][64 + 4 * tx];
            float ar[8] = {av0.x, av0.y, av0.z, av0.w, av1.x, av1.y, av1.z, av1.w};
            u64 br[4] = {bv0.x, bv0.y, bv1.x, bv1.y};
#pragma unroll
            for (int i = 0; i < 8; i++) {
                u64 ai = bcast2(ar[i]);
#pragma unroll
                for (int j = 0; j < 4; j++)
                    acc[i][j] = ffma2(ai, br[j], acc[i][j]);
            }
        }

        if (it + 1 < nIter) {
            int ns = s ^ 1;
            float av[8] = {a0.x, a0.y, a0.z, a0.w, a1.x, a1.y, a1.z, a1.w};
            float bv[8] = {b0.x, b0.y, b0.z, b0.w, b1.x, b1.y, b1.z, b1.w};
#pragma unroll
            for (int t = 0; t < 8; t++) {
                As[ns][4 * lg + t][lr] = av[t];
                Bs[ns][4 * lg + t][lr] = bv[t];
            }
            __syncthreads();
            s = ns;
        }
    }

    float4 biA = *(const float4*)&bias[n0 + 4 * tx];
    float4 biB = *(const float4*)&bias[n0 + 64 + 4 * tx];
#pragma unroll
    for (int i = 0; i < 8; i++) {
        int row = m0 + ((i < 4) ? (4 * ty + i) : (64 + 4 * ty + i - 4));
        int cb = row / cRPB;
        float* Crow = C + (long long)cb * cBS + (long long)(row - cb * cRPB) * N;
        float2 p0 = unpack2(acc[i][0]);
        float2 p1 = unpack2(acc[i][1]);
        float2 p2 = unpack2(acc[i][2]);
        float2 p3 = unpack2(acc[i][3]);
        float4 oA = make_float4(p0.x + biA.x, p0.y + biA.y, p1.x + biA.z, p1.y + biA.w);
        float4 oB = make_float4(p2.x + biB.x, p2.y + biB.y, p3.x + biB.z, p3.y + biB.w);
        *(float4*)&Crow[n0 + 4 * tx] = oA;
        *(float4*)&Crow[n0 + 64 + 4 * tx] = oB;
    }
}

// ---------------------------------------------------------------------------
// Split QKV + RMSNorm + RoPE. One warp per (b, n, head).
// ---------------------------------------------------------------------------
__global__ void __launch_bounds__(256)
qkv_post(const float* __restrict__ qs1, const float* __restrict__ ks1,
         const float* __restrict__ qs2, const float* __restrict__ ks2)
{
    int w = (blockIdx.x * blockDim.x + threadIdx.x) >> 5;
    int lane = threadIdx.x & 31;
    int h = w & 15;
    int n = (w >> 4) & (NT - 1);
    int b = w >> 15;

    const float* row = g_qkv + (long long)(b * NT + n) * (3 * DM);
    const float* qs = (n < NSEG1) ? qs1 : qs2;
    const float* ks = (n < NSEG1) ? ks1 : ks2;

    float pos = (float)n;
    float e = (float)(2 * lane) * (1.0f / 64.0f);
    float invf = expf(-e * 9.210340371976184f);
    float ang = pos * invf;
    float cs = cosf(ang), sn = sinf(ang);

    long long obase = ((long long)(b * NH + h) * NT + n) * HD + 2 * lane;
    int doff = h * HD + 2 * lane;

    {
        float2 v = *(const float2*)(row + doff);
        float ss = v.x * v.x + v.y * v.y;
#pragma unroll
        for (int off = 16; off; off >>= 1) ss += __shfl_xor_sync(0xffffffffu, ss, off);
        float inv = rsqrtf(ss * (1.0f / 64.0f) + 1e-6f);
        float a = v.x * inv * qs[2 * lane];
        float c = v.y * inv * qs[2 * lane + 1];
        float2 o = make_float2(a * cs - c * sn, a * sn + c * cs);
        *(float2*)(g_q + obase) = o;
    }
    {
        float2 v = *(const float2*)(row + DM + doff);
        float ss = v.x * v.x + v.y * v.y;
#pragma unroll
        for (int off = 16; off; off >>= 1) ss += __shfl_xor_sync(0xffffffffu, ss, off);
        float inv = rsqrtf(ss * (1.0f / 64.0f) + 1e-6f);
        float a = v.x * inv * ks[2 * lane];
        float c = v.y * inv * ks[2 * lane + 1];
        float2 o = make_float2(a * cs - c * sn, a * sn + c * cs);
        *(float2*)(g_k + obase) = o;
    }
    {
        float2 v = *(const float2*)(row + 2 * DM + doff);
        *(float2*)(g_v + obase) = v;
    }
}

// ---------------------------------------------------------------------------
// Flash attention v5: same 128x128 tile / 192KB smem map as round-5, but
// 512 threads (16 warps = 4/SMSP) to hide LDS/shfl latency.
// Micro: 4 q-rows (4ty..4ty+3) x 8 k-cols ({4tx, 64+4tx}).
// K staged through 4 float4 regs (transpose store); V via cp.async double
// buffer. P swizzled (r ^ (k & 0x1C)).
// ---------------------------------------------------------------------------
#define FA_QS   0                        // Qs[d][r]  : 64 x 128
#define FA_KS   (64 * 128)               // Ks[d][c]  : 64 x 128
#define FA_VS   (2 * 64 * 128)           // Vs[2][k][d]: 2 x 128 x 64
#define FA_PS   (FA_VS + 2 * 128 * 64)   // Ps[k][r^] : 128 x 128
#define FA_FLOATS (FA_PS + 128 * 128)
#define FA_SMEM_BYTES (FA_FLOATS * 4)

__global__ void __launch_bounds__(512, 1)
flash_attn()
{
    extern __shared__ float sm[];
    float* Qs = sm + FA_QS;
    float* Ks = sm + FA_KS;
    float* Vs = sm + FA_VS;
    float* Ps = sm + FA_PS;

    const int b = blockIdx.z, h = blockIdx.y;
    const int q0 = blockIdx.x * 128;
    const int tid = threadIdx.x;
    const int tx = tid & 15;       // k-col groups {4tx, 64+4tx}
    const int ty = tid >> 4;       // 0..31 -> q-rows 4ty..4ty+3

    const long long bh = (long long)(b * NH + h) * NT;
    const float* Qbase = g_q + bh * HD;
    const float* Kbase = g_k + bh * HD;
    const float* Vbase = g_v + bh * HD;

    const int lr = tid >> 2;       // 0..127 (row)
    const int lg = tid & 3;        // 16-float d-group

    // ---- Q fill (transposed, pre-scaled by softmax scale 1/8) ----
    {
        const float* qrow = Qbase + (long long)(q0 + lr) * HD + lg * 16;
#pragma unroll
        for (int c = 0; c < 4; c++) {
            float4 v = *(const float4*)(qrow + 4 * c);
            int d = lg * 16 + 4 * c;
            Qs[(d + 0) * 128 + lr] = v.x * 0.125f;
            Qs[(d + 1) * 128 + lr] = v.y * 0.125f;
            Qs[(d + 2) * 128 + lr] = v.z * 0.125f;
            Qs[(d + 3) * 128 + lr] = v.w * 0.125f;
        }
    }

    // ---- V cp.async mapping ----
    const float* vsrc = Vbase + (long long)lr * HD + 16 * lg;
    u32 vdst0 = (u32)__cvta_generic_to_shared(Vs + lr * 64 + 16 * lg);

    // prologue: V tile 0 async, K tile 0 regs
    {
#pragma unroll
        for (int j = 0; j < 4; j++) cp16(vdst0 + 16 * j, vsrc + 4 * j);
        cp_commit();
    }
    float4 kv[4];
    {
        const float* krow = Kbase + (long long)lr * HD + lg * 16;
#pragma unroll
        for (int c = 0; c < 4; c++) kv[c] = *(const float4*)(krow + 4 * c);
    }

    u64 oacc[4][2];
    float mreg[4], lreg[4];
#pragma unroll
    for (int i = 0; i < 4; i++) {
        mreg[i] = -1e30f; lreg[i] = 0.0f;
        oacc[i][0] = 0ull; oacc[i][1] = 0ull;
    }

    const int nTiles = NT / 128;
    for (int t = 0; t < nTiles; ++t) {
        const int s = t & 1;
        const float* Vcur = Vs + s * (128 * 64);

        __syncthreads();   // prev PV done (Ps, Vs); prev QK done with Ks; Qs fill (t=0)

        // store K_t into Ks (transposed)
#pragma unroll
        for (int c = 0; c < 4; c++) {
            int d = lg * 16 + 4 * c;
            Ks[(d + 0) * 128 + lr] = kv[c].x;
            Ks[(d + 1) * 128 + lr] = kv[c].y;
            Ks[(d + 2) * 128 + lr] = kv[c].z;
            Ks[(d + 3) * 128 + lr] = kv[c].w;
        }

        if (t + 1 < nTiles) {
            const float* vn = vsrc + (long long)(t + 1) * 128 * HD;
            u32 vd = vdst0 + (u32)((s ^ 1) * (128 * 64 * 4));
#pragma unroll
            for (int j = 0; j < 4; j++) cp16(vd + 16 * j, vn + 4 * j);
            cp_commit();
            cp_wait1();   // V_t complete
            const float* krow = Kbase + (long long)(t + 1) * 128 * HD + (long long)lr * HD + lg * 16;
#pragma unroll
            for (int c = 0; c < 4; c++) kv[c] = *(const float4*)(krow + 4 * c);
        } else {
            cp_wait0();
        }
        __syncthreads();   // Ks + Vs[s] visible

        // ---- S = Q^T K : 4x8 micro ----
        u64 sacc[4][4];
#pragma unroll
        for (int i = 0; i < 4; i++)
#pragma unroll
            for (int j = 0; j < 4; j++) sacc[i][j] = 0ull;

#pragma unroll 8
        for (int d = 0; d < 64; d++) {
            float4 av = *(const float4*)&Qs[d * 128 + 4 * ty];
            ulonglong2 bv0 = *(const ulonglong2*)&Ks[d * 128 + 4 * tx];
            ulonglong2 bv1 = *(const ulonglong2*)&Ks[d * 128 + 64 + 4 * tx];
            float ar[4] = {av.x, av.y, av.z, av.w};
            u64 br[4] = {bv0.x, bv0.y, bv1.x, bv1.y};
#pragma unroll
            for (int i = 0; i < 4; i++) {
                u64 ai = bcast2(ar[i]);
#pragma unroll
                for (int j = 0; j < 4; j++)
                    sacc[i][j] = ffma2(ai, br[j], sacc[i][j]);
            }
        }

        // ---- online softmax (rows replicated over 16-lane groups) ----
#pragma unroll
        for (int i = 0; i < 4; i++) {
            float sv[8];
            float2 tt;
            tt = unpack2(sacc[i][0]); sv[0] = tt.x; sv[1] = tt.y;
            tt = unpack2(sacc[i][1]); sv[2] = tt.x; sv[3] = tt.y;
            tt = unpack2(sacc[i][2]); sv[4] = tt.x; sv[5] = tt.y;
            tt = unpack2(sacc[i][3]); sv[6] = tt.x; sv[7] = tt.y;

            float mt = fmaxf(fmaxf(fmaxf(sv[0], sv[1]), fmaxf(sv[2], sv[3])),
                             fmaxf(fmaxf(sv[4], sv[5]), fmaxf(sv[6], sv[7])));
#pragma unroll
            for (int off = 8; off; off >>= 1) mt = fmaxf(mt, __shfl_xor_sync(0xffffffffu, mt, off));
            float nm = fmaxf(mreg[i], mt);
            float f = fexp(mreg[i] - nm);
            mreg[i] = nm;

            float p[8];
            float ts = 0.0f;
#pragma unroll
            for (int j = 0; j < 8; j++) {
                p[j] = fexp(sv[j] - nm);
                ts += p[j];
            }
#pragma unroll
            for (int off = 8; off; off >>= 1) ts += __shfl_xor_sync(0xffffffffu, ts, off);
            lreg[i] = lreg[i] * f + ts;

            u64 f2 = bcast2(f);
            oacc[i][0] = fmul2(oacc[i][0], f2);
            oacc[i][1] = fmul2(oacc[i][1], f2);

            int ri = 4 * ty + i;
#pragma unroll
            for (int j = 0; j < 8; j++) {
                int kc = (j < 4) ? (4 * tx + j) : (64 + 4 * tx + j - 4);
                Ps[kc * 128 + (ri ^ (kc & 0x1C))] = p[j];
            }
        }
        __syncthreads();   // Ps visible

        // ---- O += P V : 4 rows x 4 d-cols ----
#pragma unroll 8
        for (int k = 0; k < 128; k++) {
            int xw = k & 0x1C;
            float4 a0 = *(const float4*)&Ps[k * 128 + ((4 * ty) ^ xw)];
            ulonglong2 bv = *(const ulonglong2*)&Vcur[k * 64 + 4 * tx];
            float ar[4] = {a0.x, a0.y, a0.z, a0.w};
#pragma unroll
            for (int i = 0; i < 4; i++) {
                u64 ai = bcast2(ar[i]);
                oacc[i][0] = ffma2(ai, bv.x, oacc[i][0]);
                oacc[i][1] = ffma2(ai, bv.y, oacc[i][1]);
            }
        }
    }

    // ---- finalize: write x in (b, n, h*64 + d) layout ----
#pragma unroll
    for (int i = 0; i < 4; i++) {
        float inv = 1.0f / lreg[i];
        int row = q0 + 4 * ty + i;
        float2 p0 = unpack2(oacc[i][0]);
        float2 p1 = unpack2(oacc[i][1]);
        float4 ov = make_float4(p0.x * inv, p0.y * inv, p1.x * inv, p1.y * inv);
        *(float4*)&g_x[((long long)b * NT + row) * DM + h * HD + 4 * tx] = ov;
    }
}

// ---------------------------------------------------------------------------
// Launch
// ---------------------------------------------------------------------------
extern "C" void kernel_launch(void* const* d_in, const int* in_sizes, int n_in,
                              void* d_out, int out_size)
{
    const float* x1  = (const float*)d_in[0];
    const float* x2  = (const float*)d_in[1];
    const float* Wq1 = (const float*)d_in[2];
    const float* bq1 = (const float*)d_in[3];
    const float* Wq2 = (const float*)d_in[4];
    const float* bq2 = (const float*)d_in[5];
    const float* Wo1 = (const float*)d_in[6];
    const float* bo1 = (const float*)d_in[7];
    const float* Wo2 = (const float*)d_in[8];
    const float* bo2 = (const float*)d_in[9];
    const float* qs1 = (const float*)d_in[10];
    const float* ks1 = (const float*)d_in[11];
    const float* qs2 = (const float*)d_in[12];
    const float* ks2 = (const float*)d_in[13];
    float* out = (float*)d_out;

    float *qkv, *xbuf;
    cudaGetSymbolAddress((void**)&qkv, g_qkv);
    cudaGetSymbolAddress((void**)&xbuf, g_x);

    cudaFuncSetAttribute(flash_attn, cudaFuncAttributeMaxDynamicSharedMemorySize,
                         FA_SMEM_BYTES);

    // QKV projections into combined (b, 2048, 3072) scratch
    gemm_nt<<<dim3(3072 / 128, 3072 / 128), 256>>>(
        x1, Wq1, bq1, qkv,
        3072, 1024,
        NSEG1, (long long)NSEG1 * DM,
        NSEG1, (long long)NT * 3 * DM);
    gemm_nt<<<dim3(3072 / 128, 1024 / 128), 256>>>(
        x2, Wq2, bq2, qkv + (long long)NSEG1 * 3 * DM,
        3072, 1024,
        NSEG2, (long long)NSEG2 * DM,
        NSEG2, (long long)NT * 3 * DM);

    // Split + RMSNorm + RoPE -> g_q/g_k/g_v
    qkv_post<<<(BATCH * NT * NH) / 8, 256>>>(qs1, ks1, qs2, ks2);

    // Attention -> g_x
    flash_attn<<<dim3(NT / 128, NH, BATCH), 512, FA_SMEM_BYTES>>>();

    // Output projections (out1 then out2, concatenated in d_out)
    gemm_nt<<<dim3(1024 / 128, 3072 / 128), 256>>>(
        xbuf, Wo1, bo1, out,
        1024, 1024,
        NSEG1, (long long)NT * DM,
        NSEG1, (long long)NSEG1 * DM);
    gemm_nt<<<dim3(1024 / 128, 1024 / 128), 256>>>(
        xbuf + (long long)NSEG1 * DM, Wo2, bo2, out + (long long)BATCH * NSEG1 * DM,
        1024, 1024,
        NSEG2, (long long)NT * DM,
        NSEG2, (long long)NSEG2 * DM);
}

// round 9
// speedup vs baseline: 1.2445x; 1.2445x over previous
#include <cuda_runtime.h>
#include <cuda_bf16.h>
#include <cstdint>
#include <math.h>

#define BATCH 2
#define NT    2048
#define NSEG1 1536
#define NSEG2 512
#define DM    1024
#define NH    16
#define HD    64
#define KP    3072      // split-K: [hi | hi | lo] (A)  /  [hi | lo | hi] (B)
#define LDSB  80        // smem row stride bytes (40 bf16, pad)

typedef unsigned long long u64;
typedef unsigned int u32;

// ---------------- scratch (static, no allocation) ----------------
static __device__ float g_qkv[BATCH * NT * 3 * DM];
static __device__ float g_q[BATCH * NH * NT * HD];
static __device__ float g_k[BATCH * NH * NT * HD];
static __device__ float g_v[BATCH * NH * NT * HD];
static __device__ float g_x[BATCH * NT * DM];

// bf16 split buffers: [rows][3072]
static __device__ __nv_bfloat16 g_a1[3072 * KP];
static __device__ __nv_bfloat16 g_a2[1024 * KP];
static __device__ __nv_bfloat16 g_x2[4096 * KP];
static __device__ __nv_bfloat16 g_w1[3072 * KP];
static __device__ __nv_bfloat16 g_w2[3072 * KP];
static __device__ __nv_bfloat16 g_o1[1024 * KP];
static __device__ __nv_bfloat16 g_o2[1024 * KP];

// ---------------- packed fp32 helpers (flash) ----------------
__device__ __forceinline__ u64 ffma2(u64 a, u64 b, u64 c) {
    u64 d;
    asm("fma.rn.f32x2 %0, %1, %2, %3;" : "=l"(d) : "l"(a), "l"(b), "l"(c));
    return d;
}
__device__ __forceinline__ u64 fmul2(u64 a, u64 b) {
    u64 d;
    asm("mul.rn.f32x2 %0, %1, %2;" : "=l"(d) : "l"(a), "l"(b));
    return d;
}
__device__ __forceinline__ u64 bcast2(float x) {
    u64 r;
    asm("mov.b64 %0, {%1, %1};" : "=l"(r) : "f"(x));
    return r;
}
__device__ __forceinline__ float2 unpack2(u64 v) {
    float2 f;
    asm("mov.b64 {%0, %1}, %2;" : "=f"(f.x), "=f"(f.y) : "l"(v));
    return f;
}
__device__ __forceinline__ void cp16(u32 saddr, const void* gptr) {
    asm volatile("cp.async.ca.shared.global [%0], [%1], 16;" :: "r"(saddr), "l"(gptr));
}
__device__ __forceinline__ void cp_commit() { asm volatile("cp.async.commit_group;"); }
__device__ __forceinline__ void cp_wait1() { asm volatile("cp.async.wait_group 1;"); }
__device__ __forceinline__ void cp_wait0() { asm volatile("cp.async.wait_group 0;"); }

__device__ __forceinline__ float fexp(float x) {
    x = fmaxf(x, -80.0f);
    float t = x * 1.4426950408889634f;
    float n = rintf(t);
    float f = t - n;
    float z = f * 0.6931471805599453f;
    float p = 1.0f + z * (1.0f + z * (0.5f + z * (0.16666667f + z * (0.041666667f + z * 0.008333334f))));
    int ni = (int)n;
    float s = __int_as_float((ni + 127) << 23);
    return p * s;
}

// ---------------- mma.sync / ldmatrix helpers ----------------
__device__ __forceinline__ void ldsm4(u32* d, u32 addr) {
    asm volatile("ldmatrix.sync.aligned.m8n8.x4.shared.b16 {%0,%1,%2,%3}, [%4];"
                 : "=r"(d[0]), "=r"(d[1]), "=r"(d[2]), "=r"(d[3]) : "r"(addr));
}
__device__ __forceinline__ void mma16816(float* c, const u32* a, const u32* b) {
    asm volatile(
        "mma.sync.aligned.m16n8k16.row.col.f32.bf16.bf16.f32 "
        "{%0,%1,%2,%3}, {%4,%5,%6,%7}, {%8,%9}, {%0,%1,%2,%3};"
        : "+f"(c[0]), "+f"(c[1]), "+f"(c[2]), "+f"(c[3])
        : "r"(a[0]), "r"(a[1]), "r"(a[2]), "r"(a[3]), "r"(b[0]), "r"(b[1]));
}

// ---------------------------------------------------------------------------
// fp32 -> bf16 split, K'=3072.
// mode 0 (A operand): [hi | hi | lo]
// mode 1 (B operand): [hi | lo | hi]
// => A·B^T over K'=3072 = AhBh + AhBl + AlBh  (AlBl ~2^-18, dropped)
// ---------------------------------------------------------------------------
__global__ void __launch_bounds__(256)
cvt_split(const float4* __restrict__ in, __nv_bfloat16* __restrict__ out,
          int n4, int mode)
{
    for (int i = blockIdx.x * blockDim.x + threadIdx.x; i < n4;
         i += gridDim.x * blockDim.x) {
        float4 v = in[i];
        int row = i >> 8;          // 256 float4 per 1024-col row
        int c = (i & 255) * 4;
        __nv_bfloat16 h0 = __float2bfloat16(v.x);
        __nv_bfloat16 h1 = __float2bfloat16(v.y);
        __nv_bfloat16 h2 = __float2bfloat16(v.z);
        __nv_bfloat16 h3 = __float2bfloat16(v.w);
        __nv_bfloat16 l0 = __float2bfloat16(v.x - __bfloat162float(h0));
        __nv_bfloat16 l1 = __float2bfloat16(v.y - __bfloat162float(h1));
        __nv_bfloat16 l2 = __float2bfloat16(v.z - __bfloat162float(h2));
        __nv_bfloat16 l3 = __float2bfloat16(v.w - __bfloat162float(h3));
        u32 hu0 = (u32)__bfloat16_as_ushort(h0) | ((u32)__bfloat16_as_ushort(h1) << 16);
        u32 hu1 = (u32)__bfloat16_as_ushort(h2) | ((u32)__bfloat16_as_ushort(h3) << 16);
        u32 lu0 = (u32)__bfloat16_as_ushort(l0) | ((u32)__bfloat16_as_ushort(l1) << 16);
        u32 lu1 = (u32)__bfloat16_as_ushort(l2) | ((u32)__bfloat16_as_ushort(l3) << 16);
        uint2 hv = make_uint2(hu0, hu1);
        uint2 lv = make_uint2(lu0, lu1);
        __nv_bfloat16* base = out + (long long)row * KP + c;
        *(uint2*)(base) = hv;
        if (mode == 0) {
            *(uint2*)(base + 1024) = hv;
            *(uint2*)(base + 2048) = lv;
        } else {
            *(uint2*)(base + 1024) = lv;
            *(uint2*)(base + 2048) = hv;
        }
    }
}

// ---------------------------------------------------------------------------
// bf16 mma.sync GEMM: C[m,n] = sum_k' A[m,k']B[n,k'] + bias[n], K'=3072.
// 128x128 CTA tile, 8 warps (2M x 4N), 64x32 warp tile.
// K-chunk 32, cp.async double buffer, smem rows padded to 80B.
// ---------------------------------------------------------------------------
__global__ void __launch_bounds__(256, 2)
gemm_mma(const __nv_bfloat16* __restrict__ A, const __nv_bfloat16* __restrict__ B,
         const float* __restrict__ bias, float* __restrict__ C,
         int N, int aRPB, int aSTR, int cRPB, long long cBS)
{
    __shared__ __align__(16) char smem[2 * 2 * 128 * LDSB];   // [buf][A|B][128][80B]

    const int tid = threadIdx.x;
    const int wid = tid >> 5;
    const int lane = tid & 31;
    const int wm = wid >> 2;          // 0..1
    const int wn = wid & 3;           // 0..3
    const int m0 = blockIdx.y * 128;
    const int n0 = blockIdx.x * 128;

    const u32 smem_base = (u32)__cvta_generic_to_shared(smem);
    const u32 sA0 = smem_base;
    const u32 sB0 = smem_base + 128 * LDSB;
    const u32 bufstride = 2 * 128 * LDSB;

    // loader mapping: row r, 32B half
    const int r = tid >> 1;
    const int half = tid & 1;
    int am = m0 + r;
    int ab = am / aRPB;
    const __nv_bfloat16* asrc = A + ((long long)ab * aSTR + (am - ab * aRPB)) * KP + half * 16;
    const __nv_bfloat16* bsrc = B + (long long)(n0 + r) * KP + half * 16;
    const u32 dstoff = r * LDSB + half * 32;

    // ldmatrix thread offsets
    const u32 aoff = (lane & 15) * LDSB + (lane >> 4) * 16;
    const u32 boff = ((lane & 7) + ((lane >> 4) << 3)) * LDSB + ((lane >> 3) & 1) * 16;

    float acc[4][4][4];
#pragma unroll
    for (int i = 0; i < 4; i++)
#pragma unroll
        for (int j = 0; j < 4; j++)
#pragma unroll
            for (int q = 0; q < 4; q++) acc[i][j][q] = 0.0f;

    // prologue: chunk 0 -> buf 0
    cp16(sA0 + dstoff, asrc);
    cp16(sA0 + dstoff + 16, asrc + 8);
    cp16(sB0 + dstoff, bsrc);
    cp16(sB0 + dstoff + 16, bsrc + 8);
    cp_commit();

    const int nIter = KP / 32;   // 96
    for (int it = 0; it < nIter; ++it) {
        const int s = it & 1;
        __syncthreads();   // everyone done reading buf s^1 (prev iter's mma)

        if (it + 1 < nIter) {
            const int k0 = (it + 1) * 32;
            const u32 d = ((it + 1) & 1) * bufstride;
            cp16(sA0 + d + dstoff, asrc + k0);
            cp16(sA0 + d + dstoff + 16, asrc + k0 + 8);
            cp16(sB0 + d + dstoff, bsrc + k0);
            cp16(sB0 + d + dstoff + 16, bsrc + k0 + 8);
            cp_commit();
            cp_wait1();
        } else {
            cp_wait0();
        }
        __syncthreads();   // buf s loads visible

        const u32 sA = sA0 + s * bufstride;
        const u32 sB = sB0 + s * bufstride;
#pragma unroll
        for (int ks = 0; ks < 2; ks++) {
            u32 af[4][4], bf[2][4];
#pragma unroll
            for (int mt = 0; mt < 4; mt++)
                ldsm4(af[mt], sA + (wm * 64 + mt * 16) * LDSB + aoff + ks * 32);
#pragma unroll
            for (int np = 0; np < 2; np++)
                ldsm4(bf[np], sB + (wn * 32 + np * 16) * LDSB + boff + ks * 32);
#pragma unroll
            for (int mt = 0; mt < 4; mt++) {
#pragma unroll
                for (int nt = 0; nt < 4; nt++)
                    mma16816(acc[mt][nt], af[mt], bf[nt >> 1] + (nt & 1) * 2);
            }
        }
    }

    // epilogue: add bias, store fp32
#pragma unroll
    for (int mt = 0; mt < 4; mt++) {
        int row0 = m0 + wm * 64 + mt * 16 + (lane >> 2);
#pragma unroll
        for (int half_m = 0; half_m < 2; half_m++) {
            int row = row0 + half_m * 8;
            int cb = row / cRPB;
            float* crow = C + (long long)cb * cBS + (long long)(row - cb * cRPB) * N;
#pragma unroll
            for (int nt = 0; nt < 4; nt++) {
                int col = n0 + wn * 32 + nt * 8 + 2 * (lane & 3);
                float2 b2 = *(const float2*)(bias + col);
                float2 o = make_float2(acc[mt][nt][2 * half_m] + b2.x,
                                       acc[mt][nt][2 * half_m + 1] + b2.y);
                *(float2*)(crow + col) = o;
            }
        }
    }
}

// ---------------------------------------------------------------------------
// Split QKV + RMSNorm + RoPE. One warp per (b, n, head).
// ---------------------------------------------------------------------------
__global__ void __launch_bounds__(256)
qkv_post(const float* __restrict__ qs1, const float* __restrict__ ks1,
         const float* __restrict__ qs2, const float* __restrict__ ks2)
{
    int w = (blockIdx.x * blockDim.x + threadIdx.x) >> 5;
    int lane = threadIdx.x & 31;
    int h = w & 15;
    int n = (w >> 4) & (NT - 1);
    int b = w >> 15;

    const float* row = g_qkv + (long long)(b * NT + n) * (3 * DM);
    const float* qs = (n < NSEG1) ? qs1 : qs2;
    const float* ks = (n < NSEG1) ? ks1 : ks2;

    float pos = (float)n;
    float e = (float)(2 * lane) * (1.0f / 64.0f);
    float invf = expf(-e * 9.210340371976184f);
    float ang = pos * invf;
    float cs = cosf(ang), sn = sinf(ang);

    long long obase = ((long long)(b * NH + h) * NT + n) * HD + 2 * lane;
    int doff = h * HD + 2 * lane;

    {
        float2 v = *(const float2*)(row + doff);
        float ss = v.x * v.x + v.y * v.y;
#pragma unroll
        for (int off = 16; off; off >>= 1) ss += __shfl_xor_sync(0xffffffffu, ss, off);
        float inv = rsqrtf(ss * (1.0f / 64.0f) + 1e-6f);
        float a = v.x * inv * qs[2 * lane];
        float c = v.y * inv * qs[2 * lane + 1];
        float2 o = make_float2(a * cs - c * sn, a * sn + c * cs);
        *(float2*)(g_q + obase) = o;
    }
    {
        float2 v = *(const float2*)(row + DM + doff);
        float ss = v.x * v.x + v.y * v.y;
#pragma unroll
        for (int off = 16; off; off >>= 1) ss += __shfl_xor_sync(0xffffffffu, ss, off);
        float inv = rsqrtf(ss * (1.0f / 64.0f) + 1e-6f);
        float a = v.x * inv * ks[2 * lane];
        float c = v.y * inv * ks[2 * lane + 1];
        float2 o = make_float2(a * cs - c * sn, a * sn + c * cs);
        *(float2*)(g_k + obase) = o;
    }
    {
        float2 v = *(const float2*)(row + 2 * DM + doff);
        *(float2*)(g_v + obase) = v;
    }
}

// ---------------------------------------------------------------------------
// Flash attention (round-5 known-good): 128x128 tiles, 256 thr, packed FMA,
// cp.async V double buffer, K reg-staged transpose, P swizzled.
// ---------------------------------------------------------------------------
#define FA_QS   0
#define FA_KS   (64 * 128)
#define FA_VS   (2 * 64 * 128)
#define FA_PS   (FA_VS + 2 * 128 * 64)
#define FA_FLOATS (FA_PS + 128 * 128)
#define FA_SMEM_BYTES (FA_FLOATS * 4)

__global__ void __launch_bounds__(256, 1)
flash_attn()
{
    extern __shared__ float sm[];
    float* Qs = sm + FA_QS;
    float* Ks = sm + FA_KS;
    float* Vs = sm + FA_VS;
    float* Ps = sm + FA_PS;

    const int b = blockIdx.z, h = blockIdx.y;
    const int q0 = blockIdx.x * 128;
    const int tid = threadIdx.x;
    const int tx = tid & 15, ty = tid >> 4;

    const long long bh = (long long)(b * NH + h) * NT;
    const float* Qbase = g_q + bh * HD;
    const float* Kbase = g_k + bh * HD;
    const float* Vbase = g_v + bh * HD;

    const int lr = tid >> 1;
    const int lg = tid & 1;

    {
        const float* qrow = Qbase + (long long)(q0 + lr) * HD + lg * 32;
#pragma unroll
        for (int c = 0; c < 8; c++) {
            float4 v = *(const float4*)(qrow + 4 * c);
            int d = lg * 32 + 4 * c;
            Qs[(d + 0) * 128 + lr] = v.x * 0.125f;
            Qs[(d + 1) * 128 + lr] = v.y * 0.125f;
            Qs[(d + 2) * 128 + lr] = v.z * 0.125f;
            Qs[(d + 3) * 128 + lr] = v.w * 0.125f;
        }
    }

    const float* vsrc = Vbase + (long long)lr * HD + 32 * lg;
    u32 vdst0 = (u32)__cvta_generic_to_shared(Vs + lr * 64 + 32 * lg);

    {
#pragma unroll
        for (int j = 0; j < 8; j++) cp16(vdst0 + 16 * j, vsrc + 4 * j);
        cp_commit();
    }
    float4 kv[8];
    {
        const float* krow = Kbase + (long long)lr * HD + lg * 32;
#pragma unroll
        for (int c = 0; c < 8; c++) kv[c] = *(const float4*)(krow + 4 * c);
    }

    u64 oacc[8][2];
    float mreg[8], lreg[8];
#pragma unroll
    for (int i = 0; i < 8; i++) {
        mreg[i] = -1e30f; lreg[i] = 0.0f;
        oacc[i][0] = 0ull; oacc[i][1] = 0ull;
    }

    const int nTiles = NT / 128;
    for (int t = 0; t < nTiles; ++t) {
        const int s = t & 1;
        const float* Vcur = Vs + s * (128 * 64);

        __syncthreads();

#pragma unroll
        for (int c = 0; c < 8; c++) {
            int d = lg * 32 + 4 * c;
            Ks[(d + 0) * 128 + lr] = kv[c].x;
            Ks[(d + 1) * 128 + lr] = kv[c].y;
            Ks[(d + 2) * 128 + lr] = kv[c].z;
            Ks[(d + 3) * 128 + lr] = kv[c].w;
        }

        if (t + 1 < nTiles) {
            const float* vn = vsrc + (long long)(t + 1) * 128 * HD;
            u32 vd = vdst0 + (u32)((s ^ 1) * (128 * 64 * 4));
#pragma unroll
            for (int j = 0; j < 8; j++) cp16(vd + 16 * j, vn + 4 * j);
            cp_commit();
            cp_wait1();
            const float* krow = Kbase + (long long)(t + 1) * 128 * HD + (long long)lr * HD + lg * 32;
#pragma unroll
            for (int c = 0; c < 8; c++) kv[c] = *(const float4*)(krow + 4 * c);
        } else {
            cp_wait0();
        }
        __syncthreads();

        u64 sacc[8][4];
#pragma unroll
        for (int i = 0; i < 8; i++)
#pragma unroll
            for (int j = 0; j < 4; j++) sacc[i][j] = 0ull;

#pragma unroll 8
        for (int d = 0; d < 64; d++) {
            float4 av0 = *(const float4*)&Qs[d * 128 + 4 * ty];
            float4 av1 = *(const float4*)&Qs[d * 128 + 64 + 4 * ty];
            ulonglong2 bv0 = *(const ulonglong2*)&Ks[d * 128 + 4 * tx];
            ulonglong2 bv1 = *(const ulonglong2*)&Ks[d * 128 + 64 + 4 * tx];
            float ar[8] = {av0.x, av0.y, av0.z, av0.w, av1.x, av1.y, av1.z, av1.w};
            u64 br[4] = {bv0.x, bv0.y, bv1.x, bv1.y};
#pragma unroll
            for (int i = 0; i < 8; i++) {
                u64 ai = bcast2(ar[i]);
#pragma unroll
                for (int j = 0; j < 4; j++)
                    sacc[i][j] = ffma2(ai, br[j], sacc[i][j]);
            }
        }

#pragma unroll
        for (int i = 0; i < 8; i++) {
            float sv[8];
            float2 tt;
            tt = unpack2(sacc[i][0]); sv[0] = tt.x; sv[1] = tt.y;
            tt = unpack2(sacc[i][1]); sv[2] = tt.x; sv[3] = tt.y;
            tt = unpack2(sacc[i][2]); sv[4] = tt.x; sv[5] = tt.y;
            tt = unpack2(sacc[i][3]); sv[6] = tt.x; sv[7] = tt.y;

            float mt = fmaxf(fmaxf(fmaxf(sv[0], sv[1]), fmaxf(sv[2], sv[3])),
                             fmaxf(fmaxf(sv[4], sv[5]), fmaxf(sv[6], sv[7])));
#pragma unroll
            for (int off = 8; off; off >>= 1) mt = fmaxf(mt, __shfl_xor_sync(0xffffffffu, mt, off));
            float nm = fmaxf(mreg[i], mt);
            float f = fexp(mreg[i] - nm);
            mreg[i] = nm;

            float p[8];
            float ts = 0.0f;
#pragma unroll
            for (int j = 0; j < 8; j++) {
                p[j] = fexp(sv[j] - nm);
                ts += p[j];
            }
#pragma unroll
            for (int off = 8; off; off >>= 1) ts += __shfl_xor_sync(0xffffffffu, ts, off);
            lreg[i] = lreg[i] * f + ts;

            u64 f2 = bcast2(f);
            oacc[i][0] = fmul2(oacc[i][0], f2);
            oacc[i][1] = fmul2(oacc[i][1], f2);

            int ri = (i < 4) ? (4 * ty + i) : (64 + 4 * ty + i - 4);
#pragma unroll
            for (int j = 0; j < 8; j++) {
                int kc = (j < 4) ? (4 * tx + j) : (64 + 4 * tx + j - 4);
                Ps[kc * 128 + (ri ^ (kc & 0x1C))] = p[j];
            }
        }
        __syncthreads();

#pragma unroll 8
        for (int k = 0; k < 128; k++) {
            int xw = k & 0x1C;
            float4 a0 = *(const float4*)&Ps[k * 128 + ((4 * ty) ^ xw)];
            float4 a1 = *(const float4*)&Ps[k * 128 + 64 + ((4 * ty) ^ xw)];
            ulonglong2 bv = *(const ulonglong2*)&Vcur[k * 64 + 4 * tx];
            float ar[8] = {a0.x, a0.y, a0.z, a0.w, a1.x, a1.y, a1.z, a1.w};
#pragma unroll
            for (int i = 0; i < 8; i++) {
                u64 ai = bcast2(ar[i]);
                oacc[i][0] = ffma2(ai, bv.x, oacc[i][0]);
                oacc[i][1] = ffma2(ai, bv.y, oacc[i][1]);
            }
        }
    }

#pragma unroll
    for (int i = 0; i < 8; i++) {
        float inv = 1.0f / lreg[i];
        int row = q0 + ((i < 4) ? (4 * ty + i) : (64 + 4 * ty + i - 4));
        float2 p0 = unpack2(oacc[i][0]);
        float2 p1 = unpack2(oacc[i][1]);
        float4 ov = make_float4(p0.x * inv, p0.y * inv, p1.x * inv, p1.y * inv);
        *(float4*)&g_x[((long long)b * NT + row) * DM + h * HD + 4 * tx] = ov;
    }
}

// ---------------------------------------------------------------------------
// Launch
// ---------------------------------------------------------------------------
extern "C" void kernel_launch(void* const* d_in, const int* in_sizes, int n_in,
                              void* d_out, int out_size)
{
    const float* x1  = (const float*)d_in[0];
    const float* x2  = (const float*)d_in[1];
    const float* Wq1 = (const float*)d_in[2];
    const float* bq1 = (const float*)d_in[3];
    const float* Wq2 = (const float*)d_in[4];
    const float* bq2 = (const float*)d_in[5];
    const float* Wo1 = (const float*)d_in[6];
    const float* bo1 = (const float*)d_in[7];
    const float* Wo2 = (const float*)d_in[8];
    const float* bo2 = (const float*)d_in[9];
    const float* qs1 = (const float*)d_in[10];
    const float* ks1 = (const float*)d_in[11];
    const float* qs2 = (const float*)d_in[12];
    const float* ks2 = (const float*)d_in[13];
    float* out = (float*)d_out;

    float *qkv, *xbuf;
    cudaGetSymbolAddress((void**)&qkv, g_qkv);
    cudaGetSymbolAddress((void**)&xbuf, g_x);
    __nv_bfloat16 *a1, *a2, *x2b, *w1, *w2, *o1, *o2;
    cudaGetSymbolAddress((void**)&a1, g_a1);
    cudaGetSymbolAddress((void**)&a2, g_a2);
    cudaGetSymbolAddress((void**)&x2b, g_x2);
    cudaGetSymbolAddress((void**)&w1, g_w1);
    cudaGetSymbolAddress((void**)&w2, g_w2);
    cudaGetSymbolAddress((void**)&o1, g_o1);
    cudaGetSymbolAddress((void**)&o2, g_o2);

    cudaFuncSetAttribute(flash_attn, cudaFuncAttributeMaxDynamicSharedMemorySize,
                         FA_SMEM_BYTES);

    // --- bf16 split conversions (A: hi|hi|lo, B: hi|lo|hi) ---
    cvt_split<<<1024, 256>>>((const float4*)x1,  a1, 3072 * 1024 / 4, 0);
    cvt_split<<<1024, 256>>>((const float4*)x2,  a2, 1024 * 1024 / 4, 0);
    cvt_split<<<1024, 256>>>((const float4*)Wq1, w1, 3072 * 1024 / 4, 1);
    cvt_split<<<1024, 256>>>((const float4*)Wq2, w2, 3072 * 1024 / 4, 1);
    cvt_split<<<1024, 256>>>((const float4*)Wo1, o1, 1024 * 1024 / 4, 1);
    cvt_split<<<1024, 256>>>((const float4*)Wo2, o2, 1024 * 1024 / 4, 1);

    // --- QKV projections (tensor pipe via mma.sync) ---
    gemm_mma<<<dim3(24, 24), 256>>>(a1, w1, bq1, qkv,
        3072, 3072, 3072, NSEG1, (long long)NT * 3 * DM);
    gemm_mma<<<dim3(24, 8), 256>>>(a2, w2, bq2, qkv + (long long)NSEG1 * 3 * DM,
        3072, 1024, 1024, NSEG2, (long long)NT * 3 * DM);

    // --- split + RMSNorm + RoPE ---
    qkv_post<<<(BATCH * NT * NH) / 8, 256>>>(qs1, ks1, qs2, ks2);

    // --- attention ---
    flash_attn<<<dim3(NT / 128, NH, BATCH), 256, FA_SMEM_BYTES>>>();

    // --- convert attention output, then output projections ---
    cvt_split<<<1024, 256>>>((const float4*)xbuf, x2b, 4096 * 1024 / 4, 0);

    gemm_mma<<<dim3(8, 24), 256>>>(x2b, o1, bo1, out,
        1024, 1536, 2048, NSEG1, (long long)NSEG1 * DM);
    gemm_mma<<<dim3(8, 8), 256>>>(x2b + (long long)NSEG1 * KP, o2, bo2,
        out + (long long)BATCH * NSEG1 * DM,
        1024, 512, 2048, NSEG2, (long long)NSEG2 * DM);
}

// round 10
// speedup vs baseline: 1.9633x; 1.5776x over previous
#include <cuda_runtime.h>
#include <cuda_bf16.h>
#include <cstdint>
#include <math.h>

#define BATCH 2
#define NT    2048
#define NSEG1 1536
#define NSEG2 512
#define DM    1024
#define NH    16
#define HD    64
#define KP    3072      // gemm split-K: [hi | hi | lo] (A)  /  [hi | lo | hi] (B)
#define LDSB  80        // gemm smem row stride bytes (40 bf16, pad)

typedef unsigned long long u64;
typedef unsigned int u32;

// ---------------- scratch (static, no allocation) ----------------
static __device__ float g_qkv[BATCH * NT * 3 * DM];
static __device__ float g_x[BATCH * NT * DM];

// bf16 hi/lo attention operands (b, h, n, d)
static __device__ __nv_bfloat16 g_qh[BATCH * NH * NT * HD], g_ql[BATCH * NH * NT * HD];
static __device__ __nv_bfloat16 g_kh[BATCH * NH * NT * HD], g_kl[BATCH * NH * NT * HD];
static __device__ __nv_bfloat16 g_vh[BATCH * NH * NT * HD], g_vl[BATCH * NH * NT * HD];

// bf16 split buffers for GEMMs: [rows][3072]
static __device__ __nv_bfloat16 g_a1[3072 * KP];
static __device__ __nv_bfloat16 g_a2[1024 * KP];
static __device__ __nv_bfloat16 g_x2[4096 * KP];
static __device__ __nv_bfloat16 g_w1[3072 * KP];
static __device__ __nv_bfloat16 g_w2[3072 * KP];
static __device__ __nv_bfloat16 g_o1[1024 * KP];
static __device__ __nv_bfloat16 g_o2[1024 * KP];

// ---------------- small helpers ----------------
__device__ __forceinline__ void cp16(u32 saddr, const void* gptr) {
    asm volatile("cp.async.ca.shared.global [%0], [%1], 16;" :: "r"(saddr), "l"(gptr));
}
__device__ __forceinline__ void cp_commit() { asm volatile("cp.async.commit_group;"); }
__device__ __forceinline__ void cp_wait1() { asm volatile("cp.async.wait_group 1;"); }
__device__ __forceinline__ void cp_wait0() { asm volatile("cp.async.wait_group 0;"); }

__device__ __forceinline__ float fexp(float x) {
    x = fmaxf(x, -80.0f);
    float t = x * 1.4426950408889634f;
    float n = rintf(t);
    float f = t - n;
    float z = f * 0.6931471805599453f;
    float p = 1.0f + z * (1.0f + z * (0.5f + z * (0.16666667f + z * (0.041666667f + z * 0.008333334f))));
    int ni = (int)n;
    float s = __int_as_float((ni + 127) << 23);
    return p * s;
}

__device__ __forceinline__ void ldsm4(u32* d, u32 addr) {
    asm volatile("ldmatrix.sync.aligned.m8n8.x4.shared.b16 {%0,%1,%2,%3}, [%4];"
                 : "=r"(d[0]), "=r"(d[1]), "=r"(d[2]), "=r"(d[3]) : "r"(addr));
}
__device__ __forceinline__ void ldsm4t(u32* d, u32 addr) {
    asm volatile("ldmatrix.sync.aligned.m8n8.x4.trans.shared.b16 {%0,%1,%2,%3}, [%4];"
                 : "=r"(d[0]), "=r"(d[1]), "=r"(d[2]), "=r"(d[3]) : "r"(addr));
}
__device__ __forceinline__ void mma16816(float* c, const u32* a, const u32* b) {
    asm volatile(
        "mma.sync.aligned.m16n8k16.row.col.f32.bf16.bf16.f32 "
        "{%0,%1,%2,%3}, {%4,%5,%6,%7}, {%8,%9}, {%0,%1,%2,%3};"
        : "+f"(c[0]), "+f"(c[1]), "+f"(c[2]), "+f"(c[3])
        : "r"(a[0]), "r"(a[1]), "r"(a[2]), "r"(a[3]), "r"(b[0]), "r"(b[1]));
}

// pack two fp32 into bf16x2 (lo = p0) and residual bf16x2
__device__ __forceinline__ void split_pack(float p0, float p1, u32& hi, u32& lo) {
    u32 hp;
    asm("cvt.rn.bf16x2.f32 %0, %1, %2;" : "=r"(hp) : "f"(p1), "f"(p0));
    float r0 = p0 - __uint_as_float(hp << 16);
    float r1 = p1 - __uint_as_float(hp & 0xFFFF0000u);
    u32 lp;
    asm("cvt.rn.bf16x2.f32 %0, %1, %2;" : "=r"(lp) : "f"(r1), "f"(r0));
    hi = hp; lo = lp;
}

// ---------------------------------------------------------------------------
// fp32 -> bf16 split for GEMMs, K'=3072. mode 0: [hi|hi|lo], mode 1: [hi|lo|hi]
// ---------------------------------------------------------------------------
__global__ void __launch_bounds__(256)
cvt_split(const float4* __restrict__ in, __nv_bfloat16* __restrict__ out,
          int n4, int mode)
{
    for (int i = blockIdx.x * blockDim.x + threadIdx.x; i < n4;
         i += gridDim.x * blockDim.x) {
        float4 v = in[i];
        int row = i >> 8;
        int c = (i & 255) * 4;
        u32 h01, l01, h23, l23;
        split_pack(v.x, v.y, h01, l01);
        split_pack(v.z, v.w, h23, l23);
        uint2 hv = make_uint2(h01, h23);
        uint2 lv = make_uint2(l01, l23);
        __nv_bfloat16* base = out + (long long)row * KP + c;
        *(uint2*)(base) = hv;
        if (mode == 0) {
            *(uint2*)(base + 1024) = hv;
            *(uint2*)(base + 2048) = lv;
        } else {
            *(uint2*)(base + 1024) = lv;
            *(uint2*)(base + 2048) = hv;
        }
    }
}

// ---------------------------------------------------------------------------
// bf16 mma.sync GEMM (round-9 verified): K'=3072, 128x128 CTA, 8 warps.
// ---------------------------------------------------------------------------
__global__ void __launch_bounds__(256, 2)
gemm_mma(const __nv_bfloat16* __restrict__ A, const __nv_bfloat16* __restrict__ B,
         const float* __restrict__ bias, float* __restrict__ C,
         int N, int aRPB, int aSTR, int cRPB, long long cBS)
{
    __shared__ __align__(16) char smem[2 * 2 * 128 * LDSB];

    const int tid = threadIdx.x;
    const int wid = tid >> 5;
    const int lane = tid & 31;
    const int wm = wid >> 2;
    const int wn = wid & 3;
    const int m0 = blockIdx.y * 128;
    const int n0 = blockIdx.x * 128;

    const u32 smem_base = (u32)__cvta_generic_to_shared(smem);
    const u32 sA0 = smem_base;
    const u32 sB0 = smem_base + 128 * LDSB;
    const u32 bufstride = 2 * 128 * LDSB;

    const int r = tid >> 1;
    const int half = tid & 1;
    int am = m0 + r;
    int ab = am / aRPB;
    const __nv_bfloat16* asrc = A + ((long long)ab * aSTR + (am - ab * aRPB)) * KP + half * 16;
    const __nv_bfloat16* bsrc = B + (long long)(n0 + r) * KP + half * 16;
    const u32 dstoff = r * LDSB + half * 32;

    const u32 aoff = (lane & 15) * LDSB + (lane >> 4) * 16;
    const u32 boff = ((lane & 7) + ((lane >> 4) << 3)) * LDSB + ((lane >> 3) & 1) * 16;

    float acc[4][4][4];
#pragma unroll
    for (int i = 0; i < 4; i++)
#pragma unroll
        for (int j = 0; j < 4; j++)
#pragma unroll
            for (int q = 0; q < 4; q++) acc[i][j][q] = 0.0f;

    cp16(sA0 + dstoff, asrc);
    cp16(sA0 + dstoff + 16, asrc + 8);
    cp16(sB0 + dstoff, bsrc);
    cp16(sB0 + dstoff + 16, bsrc + 8);
    cp_commit();

    const int nIter = KP / 32;
    for (int it = 0; it < nIter; ++it) {
        const int s = it & 1;
        __syncthreads();

        if (it + 1 < nIter) {
            const int k0 = (it + 1) * 32;
            const u32 d = ((it + 1) & 1) * bufstride;
            cp16(sA0 + d + dstoff, asrc + k0);
            cp16(sA0 + d + dstoff + 16, asrc + k0 + 8);
            cp16(sB0 + d + dstoff, bsrc + k0);
            cp16(sB0 + d + dstoff + 16, bsrc + k0 + 8);
            cp_commit();
            cp_wait1();
        } else {
            cp_wait0();
        }
        __syncthreads();

        const u32 sA = sA0 + s * bufstride;
        const u32 sB = sB0 + s * bufstride;
#pragma unroll
        for (int ks = 0; ks < 2; ks++) {
            u32 af[4][4], bf[2][4];
#pragma unroll
            for (int mt = 0; mt < 4; mt++)
                ldsm4(af[mt], sA + (wm * 64 + mt * 16) * LDSB + aoff + ks * 32);
#pragma unroll
            for (int np = 0; np < 2; np++)
                ldsm4(bf[np], sB + (wn * 32 + np * 16) * LDSB + boff + ks * 32);
#pragma unroll
            for (int mt = 0; mt < 4; mt++) {
#pragma unroll
                for (int nt = 0; nt < 4; nt++)
                    mma16816(acc[mt][nt], af[mt], bf[nt >> 1] + (nt & 1) * 2);
            }
        }
    }

#pragma unroll
    for (int mt = 0; mt < 4; mt++) {
        int row0 = m0 + wm * 64 + mt * 16 + (lane >> 2);
#pragma unroll
        for (int half_m = 0; half_m < 2; half_m++) {
            int row = row0 + half_m * 8;
            int cb = row / cRPB;
            float* crow = C + (long long)cb * cBS + (long long)(row - cb * cRPB) * N;
#pragma unroll
            for (int nt = 0; nt < 4; nt++) {
                int col = n0 + wn * 32 + nt * 8 + 2 * (lane & 3);
                float2 b2 = *(const float2*)(bias + col);
                float2 o = make_float2(acc[mt][nt][2 * half_m] + b2.x,
                                       acc[mt][nt][2 * half_m + 1] + b2.y);
                *(float2*)(crow + col) = o;
            }
        }
    }
}

// ---------------------------------------------------------------------------
// Split QKV + RMSNorm + RoPE -> bf16 hi/lo operand buffers.
// One warp per (b, n, head); Q pre-scaled by softmax scale 1/8.
// ---------------------------------------------------------------------------
__global__ void __launch_bounds__(256)
qkv_post(const float* __restrict__ qs1, const float* __restrict__ ks1,
         const float* __restrict__ qs2, const float* __restrict__ ks2)
{
    int w = (blockIdx.x * blockDim.x + threadIdx.x) >> 5;
    int lane = threadIdx.x & 31;
    int h = w & 15;
    int n = (w >> 4) & (NT - 1);
    int b = w >> 15;

    const float* row = g_qkv + (long long)(b * NT + n) * (3 * DM);
    const float* qs = (n < NSEG1) ? qs1 : qs2;
    const float* ks = (n < NSEG1) ? ks1 : ks2;

    float pos = (float)n;
    float e = (float)(2 * lane) * (1.0f / 64.0f);
    float invf = expf(-e * 9.210340371976184f);
    float ang = pos * invf;
    float cs = cosf(ang), sn = sinf(ang);

    long long obase = ((long long)(b * NH + h) * NT + n) * HD + 2 * lane;
    int doff = h * HD + 2 * lane;

    // Q (scaled 1/8)
    {
        float2 v = *(const float2*)(row + doff);
        float ss = v.x * v.x + v.y * v.y;
#pragma unroll
        for (int off = 16; off; off >>= 1) ss += __shfl_xor_sync(0xffffffffu, ss, off);
        float inv = rsqrtf(ss * (1.0f / 64.0f) + 1e-6f);
        float a = v.x * inv * qs[2 * lane];
        float c = v.y * inv * qs[2 * lane + 1];
        float ox = (a * cs - c * sn) * 0.125f;
        float oy = (a * sn + c * cs) * 0.125f;
        u32 hp, lp;
        split_pack(ox, oy, hp, lp);
        *(u32*)(g_qh + obase) = hp;
        *(u32*)(g_ql + obase) = lp;
    }
    // K
    {
        float2 v = *(const float2*)(row + DM + doff);
        float ss = v.x * v.x + v.y * v.y;
#pragma unroll
        for (int off = 16; off; off >>= 1) ss += __shfl_xor_sync(0xffffffffu, ss, off);
        float inv = rsqrtf(ss * (1.0f / 64.0f) + 1e-6f);
        float a = v.x * inv * ks[2 * lane];
        float c = v.y * inv * ks[2 * lane + 1];
        float ox = a * cs - c * sn;
        float oy = a * sn + c * cs;
        u32 hp, lp;
        split_pack(ox, oy, hp, lp);
        *(u32*)(g_kh + obase) = hp;
        *(u32*)(g_kl + obase) = lp;
    }
    // V
    {
        float2 v = *(const float2*)(row + 2 * DM + doff);
        u32 hp, lp;
        split_pack(v.x, v.y, hp, lp);
        *(u32*)(g_vh + obase) = hp;
        *(u32*)(g_vl + obase) = lp;
    }
}

// ---------------------------------------------------------------------------
// Flash attention on the tensor pipe (mma.sync bf16, split precision).
// 128 q-rows per CTA, 8 warps each owning 16 rows x all 128 keys per tile.
// S = QhKh + QlKh + QhKl ; PV = PhVh + PlVh + PhVl ; fp32 softmax in frags.
// smem: Qh/Ql resident + double-buffered Kh/Kl/Vh/Vl, 144B row stride.
// ---------------------------------------------------------------------------
#define FTILE 18432                    // 128 rows x 144 B
#define FSQH  0
#define FSQL  FTILE
#define FSKV  (2 * FTILE)
#define FBUF  (4 * FTILE)              // Kh,Kl,Vh,Vl per buffer
#define FA_SMEM (FSKV + 2 * FBUF)      // 184320 B

__global__ void __launch_bounds__(256, 1)
flash_attn()
{
    extern __shared__ char smx[];
    const u32 sbase = (u32)__cvta_generic_to_shared(smx);
    const int b = blockIdx.z, h = blockIdx.y;
    const int q0 = blockIdx.x * 128;
    const int tid = threadIdx.x;
    const int w = tid >> 5;
    const int lane = tid & 31;

    const long long bh = (long long)(b * NH + h) * NT;

    // loader mapping: row r, 64B half hf (4 x cp16 per tile)
    const int r = tid >> 1;
    const int hf = tid & 1;
    const u32 ldst = r * 144 + hf * 64;
    const __nv_bfloat16* qh_s = g_qh + (bh + q0 + r) * HD + hf * 32;
    const __nv_bfloat16* ql_s = g_ql + (bh + q0 + r) * HD + hf * 32;
    const __nv_bfloat16* kh_s = g_kh + (bh + r) * HD + hf * 32;
    const __nv_bfloat16* kl_s = g_kl + (bh + r) * HD + hf * 32;
    const __nv_bfloat16* vh_s = g_vh + (bh + r) * HD + hf * 32;
    const __nv_bfloat16* vl_s = g_vl + (bh + r) * HD + hf * 32;

    // prologue: Q tiles + KV tile 0
#pragma unroll
    for (int j = 0; j < 4; j++) {
        cp16(sbase + FSQH + ldst + 16 * j, qh_s + 8 * j);
        cp16(sbase + FSQL + ldst + 16 * j, ql_s + 8 * j);
    }
    cp_commit();
#pragma unroll
    for (int j = 0; j < 4; j++) {
        cp16(sbase + FSKV + 0 * FTILE + ldst + 16 * j, kh_s + 8 * j);
        cp16(sbase + FSKV + 1 * FTILE + ldst + 16 * j, kl_s + 8 * j);
        cp16(sbase + FSKV + 2 * FTILE + ldst + 16 * j, vh_s + 8 * j);
        cp16(sbase + FSKV + 3 * FTILE + ldst + 16 * j, vl_s + 8 * j);
    }
    cp_commit();

    // ldmatrix offsets (144B stride)
    const u32 aoff = (lane & 15) * 144 + (lane >> 4) * 16;
    const u32 boff = ((lane & 7) + ((lane >> 4) << 3)) * 144 + ((lane >> 3) & 1) * 16;
    const u32 voff = ((lane & 7) + ((lane >> 3) & 1) * 8) * 144 + (lane >> 4) * 16;

    u32 qfh[4][4], qfl[4][4];
    float o[8][4];
    float m0 = -1e30f, m1 = -1e30f, l0 = 0.0f, l1 = 0.0f;
#pragma unroll
    for (int i = 0; i < 8; i++)
#pragma unroll
        for (int q = 0; q < 4; q++) o[i][q] = 0.0f;

    const int nTiles = NT / 128;
    for (int t = 0; t < nTiles; ++t) {
        const int s = t & 1;

        if (t + 1 < nTiles) {
            const long long roff = (long long)(t + 1) * 128 * HD;
            const u32 dbuf = sbase + FSKV + ((t + 1) & 1) * FBUF;
#pragma unroll
            for (int j = 0; j < 4; j++) {
                cp16(dbuf + 0 * FTILE + ldst + 16 * j, kh_s + roff + 8 * j);
                cp16(dbuf + 1 * FTILE + ldst + 16 * j, kl_s + roff + 8 * j);
                cp16(dbuf + 2 * FTILE + ldst + 16 * j, vh_s + roff + 8 * j);
                cp16(dbuf + 3 * FTILE + ldst + 16 * j, vl_s + roff + 8 * j);
            }
            cp_commit();
            cp_wait1();
        } else {
            cp_wait0();
        }
        __syncthreads();   // KV[t] (and Q, first iter) visible

        if (t == 0) {
            const u32 qbh = sbase + FSQH + w * 16 * 144;
            const u32 qbl = sbase + FSQL + w * 16 * 144;
#pragma unroll
            for (int kc = 0; kc < 4; kc++) {
                ldsm4(qfh[kc], qbh + kc * 32 + aoff);
                ldsm4(qfl[kc], qbl + kc * 32 + aoff);
            }
        }

        const u32 skh = sbase + FSKV + s * FBUF;
        const u32 skl = skh + FTILE;
        const u32 svh = skh + 2 * FTILE;
        const u32 svl = skh + 3 * FTILE;

        // ---- S = Q K^T (16 rows x 128 keys per warp) ----
        float sc[16][4];
#pragma unroll
        for (int nt = 0; nt < 16; nt++)
#pragma unroll
            for (int q = 0; q < 4; q++) sc[nt][q] = 0.0f;

#pragma unroll
        for (int np = 0; np < 8; np++) {
#pragma unroll
            for (int kc = 0; kc < 4; kc++) {
                u32 bh4[4], bl4[4];
                ldsm4(bh4, skh + np * 16 * 144 + kc * 32 + boff);
                ldsm4(bl4, skl + np * 16 * 144 + kc * 32 + boff);
                mma16816(sc[2 * np],     qfh[kc], bh4);
                mma16816(sc[2 * np],     qfl[kc], bh4);
                mma16816(sc[2 * np],     qfh[kc], bl4);
                mma16816(sc[2 * np + 1], qfh[kc], bh4 + 2);
                mma16816(sc[2 * np + 1], qfl[kc], bh4 + 2);
                mma16816(sc[2 * np + 1], qfh[kc], bl4 + 2);
            }
        }

        // ---- online softmax (rows r0 = frag row, r1 = r0+8) ----
        float mt0 = sc[0][0], mt1 = sc[0][2];
#pragma unroll
        for (int nt = 0; nt < 16; nt++) {
            mt0 = fmaxf(mt0, fmaxf(sc[nt][0], sc[nt][1]));
            mt1 = fmaxf(mt1, fmaxf(sc[nt][2], sc[nt][3]));
        }
        mt0 = fmaxf(mt0, __shfl_xor_sync(0xffffffffu, mt0, 1));
        mt0 = fmaxf(mt0, __shfl_xor_sync(0xffffffffu, mt0, 2));
        mt1 = fmaxf(mt1, __shfl_xor_sync(0xffffffffu, mt1, 1));
        mt1 = fmaxf(mt1, __shfl_xor_sync(0xffffffffu, mt1, 2));
        float nm0 = fmaxf(m0, mt0), nm1 = fmaxf(m1, mt1);
        float f0 = fexp(m0 - nm0), f1 = fexp(m1 - nm1);
        m0 = nm0; m1 = nm1;

        float ts0 = 0.0f, ts1 = 0.0f;
#pragma unroll
        for (int nt = 0; nt < 16; nt++) {
            sc[nt][0] = fexp(sc[nt][0] - nm0);
            sc[nt][1] = fexp(sc[nt][1] - nm0);
            sc[nt][2] = fexp(sc[nt][2] - nm1);
            sc[nt][3] = fexp(sc[nt][3] - nm1);
            ts0 += sc[nt][0] + sc[nt][1];
            ts1 += sc[nt][2] + sc[nt][3];
        }
        ts0 += __shfl_xor_sync(0xffffffffu, ts0, 1);
        ts0 += __shfl_xor_sync(0xffffffffu, ts0, 2);
        ts1 += __shfl_xor_sync(0xffffffffu, ts1, 1);
        ts1 += __shfl_xor_sync(0xffffffffu, ts1, 2);
        l0 = l0 * f0 + ts0;
        l1 = l1 * f1 + ts1;

#pragma unroll
        for (int nt = 0; nt < 8; nt++) {
            o[nt][0] *= f0; o[nt][1] *= f0;
            o[nt][2] *= f1; o[nt][3] *= f1;
        }

        // ---- O += P V (P split to bf16 hi/lo A-fragments in regs) ----
#pragma unroll
        for (int kc = 0; kc < 8; kc++) {
            u32 ah[4], al[4];
            split_pack(sc[2 * kc][0],     sc[2 * kc][1],     ah[0], al[0]);
            split_pack(sc[2 * kc][2],     sc[2 * kc][3],     ah[1], al[1]);
            split_pack(sc[2 * kc + 1][0], sc[2 * kc + 1][1], ah[2], al[2]);
            split_pack(sc[2 * kc + 1][2], sc[2 * kc + 1][3], ah[3], al[3]);
#pragma unroll
            for (int vp = 0; vp < 4; vp++) {
                u32 vh4[4], vl4[4];
                ldsm4t(vh4, svh + kc * 16 * 144 + vp * 32 + voff);
                ldsm4t(vl4, svl + kc * 16 * 144 + vp * 32 + voff);
                mma16816(o[2 * vp],     ah, vh4);
                mma16816(o[2 * vp],     al, vh4);
                mma16816(o[2 * vp],     ah, vl4);
                mma16816(o[2 * vp + 1], ah, vh4 + 2);
                mma16816(o[2 * vp + 1], al, vh4 + 2);
                mma16816(o[2 * vp + 1], ah, vl4 + 2);
            }
        }
        __syncthreads();   // all warps done reading buf s before next prefetch overwrites
    }

    // ---- finalize ----
    float inv0 = 1.0f / l0, inv1 = 1.0f / l1;
    int r0g = q0 + w * 16 + (lane >> 2);
    long long base0 = ((long long)b * NT + r0g) * DM + h * HD + 2 * (lane & 3);
#pragma unroll
    for (int nt = 0; nt < 8; nt++) {
        *(float2*)&g_x[base0 + 8 * nt] =
            make_float2(o[nt][0] * inv0, o[nt][1] * inv0);
        *(float2*)&g_x[base0 + 8 * (long long)DM + 8 * nt] =
            make_float2(o[nt][2] * inv1, o[nt][3] * inv1);
    }
}

// ---------------------------------------------------------------------------
// Launch
// ---------------------------------------------------------------------------
extern "C" void kernel_launch(void* const* d_in, const int* in_sizes, int n_in,
                              void* d_out, int out_size)
{
    const float* x1  = (const float*)d_in[0];
    const float* x2  = (const float*)d_in[1];
    const float* Wq1 = (const float*)d_in[2];
    const float* bq1 = (const float*)d_in[3];
    const float* Wq2 = (const float*)d_in[4];
    const float* bq2 = (const float*)d_in[5];
    const float* Wo1 = (const float*)d_in[6];
    const float* bo1 = (const float*)d_in[7];
    const float* Wo2 = (const float*)d_in[8];
    const float* bo2 = (const float*)d_in[9];
    const float* qs1 = (const float*)d_in[10];
    const float* ks1 = (const float*)d_in[11];
    const float* qs2 = (const float*)d_in[12];
    const float* ks2 = (const float*)d_in[13];
    float* out = (float*)d_out;

    float *qkv, *xbuf;
    cudaGetSymbolAddress((void**)&qkv, g_qkv);
    cudaGetSymbolAddress((void**)&xbuf, g_x);
    __nv_bfloat16 *a1, *a2, *x2b, *w1, *w2, *o1, *o2;
    cudaGetSymbolAddress((void**)&a1, g_a1);
    cudaGetSymbolAddress((void**)&a2, g_a2);
    cudaGetSymbolAddress((void**)&x2b, g_x2);
    cudaGetSymbolAddress((void**)&w1, g_w1);
    cudaGetSymbolAddress((void**)&w2, g_w2);
    cudaGetSymbolAddress((void**)&o1, g_o1);
    cudaGetSymbolAddress((void**)&o2, g_o2);

    cudaFuncSetAttribute(flash_attn, cudaFuncAttributeMaxDynamicSharedMemorySize,
                         FA_SMEM);

    // --- bf16 split conversions (A: hi|hi|lo, B: hi|lo|hi) ---
    cvt_split<<<1024, 256>>>((const float4*)x1,  a1, 3072 * 1024 / 4, 0);
    cvt_split<<<1024, 256>>>((const float4*)x2,  a2, 1024 * 1024 / 4, 0);
    cvt_split<<<1024, 256>>>((const float4*)Wq1, w1, 3072 * 1024 / 4, 1);
    cvt_split<<<1024, 256>>>((const float4*)Wq2, w2, 3072 * 1024 / 4, 1);
    cvt_split<<<1024, 256>>>((const float4*)Wo1, o1, 1024 * 1024 / 4, 1);
    cvt_split<<<1024, 256>>>((const float4*)Wo2, o2, 1024 * 1024 / 4, 1);

    // --- QKV projections (tensor pipe) ---
    gemm_mma<<<dim3(24, 24), 256>>>(a1, w1, bq1, qkv,
        3072, 3072, 3072, NSEG1, (long long)NT * 3 * DM);
    gemm_mma<<<dim3(24, 8), 256>>>(a2, w2, bq2, qkv + (long long)NSEG1 * 3 * DM,
        3072, 1024, 1024, NSEG2, (long long)NT * 3 * DM);

    // --- split + RMSNorm + RoPE -> bf16 hi/lo operands ---
    qkv_post<<<(BATCH * NT * NH) / 8, 256>>>(qs1, ks1, qs2, ks2);

    // --- attention (tensor pipe) ---
    flash_attn<<<dim3(NT / 128, NH, BATCH), 256, FA_SMEM>>>();

    // --- convert attention output, then output projections ---
    cvt_split<<<1024, 256>>>((const float4*)xbuf, x2b, 4096 * 1024 / 4, 0);

    gemm_mma<<<dim3(8, 24), 256>>>(x2b, o1, bo1, out,
        1024, 1536, 2048, NSEG1, (long long)NSEG1 * DM);
    gemm_mma<<<dim3(8, 8), 256>>>(x2b + (long long)NSEG1 * KP, o2, bo2,
        out + (long long)BATCH * NSEG1 * DM,
        1024, 512, 2048, NSEG2, (long long)NSEG2 * DM);
}

// round 11
// speedup vs baseline: 2.1433x; 1.0917x over previous
#include <cuda_runtime.h>
#include <cuda_bf16.h>
#include <cstdint>
#include <math.h>

#define BATCH 2
#define NT    2048
#define NSEG1 1536
#define NSEG2 512
#define DM    1024
#define NH    16
#define HD    64
#define KP    3072      // gemm split-K: [hi | hi | lo] (A)  /  [hi | lo | hi] (B)
#define GLD   144       // gemm smem row stride bytes (64 bf16 + 16B pad)

typedef unsigned long long u64;
typedef unsigned int u32;

// ---------------- scratch (static, no allocation) ----------------
static __device__ float g_qkv[BATCH * NT * 3 * DM];

// bf16 hi/lo attention operands (b, h, n, d)
static __device__ __nv_bfloat16 g_qh[BATCH * NH * NT * HD], g_ql[BATCH * NH * NT * HD];
static __device__ __nv_bfloat16 g_kh[BATCH * NH * NT * HD], g_kl[BATCH * NH * NT * HD];
static __device__ __nv_bfloat16 g_vh[BATCH * NH * NT * HD], g_vl[BATCH * NH * NT * HD];

// bf16 split buffers for GEMMs: [rows][3072]
static __device__ __nv_bfloat16 g_a1[3072 * KP];
static __device__ __nv_bfloat16 g_a2[1024 * KP];
static __device__ __nv_bfloat16 g_x2[4096 * KP];
static __device__ __nv_bfloat16 g_w1[3072 * KP];
static __device__ __nv_bfloat16 g_w2[3072 * KP];
static __device__ __nv_bfloat16 g_o1[1024 * KP];
static __device__ __nv_bfloat16 g_o2[1024 * KP];

// ---------------- small helpers ----------------
__device__ __forceinline__ void cp16(u32 saddr, const void* gptr) {
    asm volatile("cp.async.ca.shared.global [%0], [%1], 16;" :: "r"(saddr), "l"(gptr));
}
__device__ __forceinline__ void cp_commit() { asm volatile("cp.async.commit_group;"); }
__device__ __forceinline__ void cp_wait1() { asm volatile("cp.async.wait_group 1;"); }
__device__ __forceinline__ void cp_wait0() { asm volatile("cp.async.wait_group 0;"); }

__device__ __forceinline__ float fexp(float x) {
    x = fmaxf(x, -80.0f);
    float t = x * 1.4426950408889634f;
    float n = rintf(t);
    float f = t - n;
    float z = f * 0.6931471805599453f;
    float p = 1.0f + z * (1.0f + z * (0.5f + z * (0.16666667f + z * (0.041666667f + z * 0.008333334f))));
    int ni = (int)n;
    float s = __int_as_float((ni + 127) << 23);
    return p * s;
}

__device__ __forceinline__ void ldsm4(u32* d, u32 addr) {
    asm volatile("ldmatrix.sync.aligned.m8n8.x4.shared.b16 {%0,%1,%2,%3}, [%4];"
                 : "=r"(d[0]), "=r"(d[1]), "=r"(d[2]), "=r"(d[3]) : "r"(addr));
}
__device__ __forceinline__ void ldsm4t(u32* d, u32 addr) {
    asm volatile("ldmatrix.sync.aligned.m8n8.x4.trans.shared.b16 {%0,%1,%2,%3}, [%4];"
                 : "=r"(d[0]), "=r"(d[1]), "=r"(d[2]), "=r"(d[3]) : "r"(addr));
}
__device__ __forceinline__ void mma16816(float* c, const u32* a, const u32* b) {
    asm volatile(
        "mma.sync.aligned.m16n8k16.row.col.f32.bf16.bf16.f32 "
        "{%0,%1,%2,%3}, {%4,%5,%6,%7}, {%8,%9}, {%0,%1,%2,%3};"
        : "+f"(c[0]), "+f"(c[1]), "+f"(c[2]), "+f"(c[3])
        : "r"(a[0]), "r"(a[1]), "r"(a[2]), "r"(a[3]), "r"(b[0]), "r"(b[1]));
}

// pack two fp32 into bf16x2 (lo half = p0) and residual bf16x2
__device__ __forceinline__ void split_pack(float p0, float p1, u32& hi, u32& lo) {
    u32 hp;
    asm("cvt.rn.bf16x2.f32 %0, %1, %2;" : "=r"(hp) : "f"(p1), "f"(p0));
    float r0 = p0 - __uint_as_float(hp << 16);
    float r1 = p1 - __uint_as_float(hp & 0xFFFF0000u);
    u32 lp;
    asm("cvt.rn.bf16x2.f32 %0, %1, %2;" : "=r"(lp) : "f"(r1), "f"(r0));
    hi = hp; lo = lp;
}

// ---------------------------------------------------------------------------
// fp32 -> bf16 split for GEMMs, K'=3072. mode 0: [hi|hi|lo], mode 1: [hi|lo|hi]
// ---------------------------------------------------------------------------
__global__ void __launch_bounds__(256)
cvt_split(const float4* __restrict__ in, __nv_bfloat16* __restrict__ out,
          int n4, int mode)
{
    for (int i = blockIdx.x * blockDim.x + threadIdx.x; i < n4;
         i += gridDim.x * blockDim.x) {
        float4 v = in[i];
        int row = i >> 8;
        int c = (i & 255) * 4;
        u32 h01, l01, h23, l23;
        split_pack(v.x, v.y, h01, l01);
        split_pack(v.z, v.w, h23, l23);
        uint2 hv = make_uint2(h01, h23);
        uint2 lv = make_uint2(l01, l23);
        __nv_bfloat16* base = out + (long long)row * KP + c;
        *(uint2*)(base) = hv;
        if (mode == 0) {
            *(uint2*)(base + 1024) = hv;
            *(uint2*)(base + 2048) = lv;
        } else {
            *(uint2*)(base + 1024) = lv;
            *(uint2*)(base + 2048) = hv;
        }
    }
}

// ---------------------------------------------------------------------------
// bf16 mma.sync GEMM, two segments merged in one launch (blockIdx.y split).
// K'=3072, 128x128 CTA tile, 8 warps, K-chunk 64, cp.async double buffer.
// Dynamic smem: 2 bufs x (A+B) x 128 rows x 144B = 73728 B.
// ---------------------------------------------------------------------------
#define GSMEM (2 * 2 * 128 * GLD)

__global__ void __launch_bounds__(256, 2)
gemm_mma2(const __nv_bfloat16* __restrict__ A0, const __nv_bfloat16* __restrict__ B0,
          const float* __restrict__ bias0, float* __restrict__ C0,
          int aRPB0, int aSTR0, int cRPB0, long long cBS0,
          const __nv_bfloat16* __restrict__ A1, const __nv_bfloat16* __restrict__ B1,
          const float* __restrict__ bias1, float* __restrict__ C1,
          int aRPB1, int aSTR1, int cRPB1, long long cBS1,
          int N, int mSplit)
{
    extern __shared__ __align__(16) char gsm[];

    const int tid = threadIdx.x;
    const int wid = tid >> 5;
    const int lane = tid & 31;
    const int wm = wid >> 2;
    const int wn = wid & 3;
    const int n0 = blockIdx.x * 128;

    const __nv_bfloat16 *A, *B;
    const float* bias;
    float* C;
    int aRPB, aSTR, cRPB;
    long long cBS;
    int m0;
    if ((int)blockIdx.y < mSplit) {
        A = A0; B = B0; bias = bias0; C = C0;
        aRPB = aRPB0; aSTR = aSTR0; cRPB = cRPB0; cBS = cBS0;
        m0 = blockIdx.y * 128;
    } else {
        A = A1; B = B1; bias = bias1; C = C1;
        aRPB = aRPB1; aSTR = aSTR1; cRPB = cRPB1; cBS = cBS1;
        m0 = (blockIdx.y - mSplit) * 128;
    }

    const u32 smem_base = (u32)__cvta_generic_to_shared(gsm);
    const u32 sA0 = smem_base;
    const u32 sB0 = smem_base + 128 * GLD;
    const u32 bufstride = 2 * 128 * GLD;

    // loader: row r, 64B half hf; 4 cp16 per operand per chunk (64 cols)
    const int r = tid >> 1;
    const int hf = tid & 1;
    int am = m0 + r;
    int ab = am / aRPB;
    const __nv_bfloat16* asrc = A + ((long long)ab * aSTR + (am - ab * aRPB)) * KP + hf * 32;
    const __nv_bfloat16* bsrc = B + (long long)(n0 + r) * KP + hf * 32;
    const u32 dstoff = r * GLD + hf * 64;

    const u32 aoff = (lane & 15) * GLD + (lane >> 4) * 16;
    const u32 boff = ((lane & 7) + ((lane >> 4) << 3)) * GLD + ((lane >> 3) & 1) * 16;

    float acc[4][4][4];
#pragma unroll
    for (int i = 0; i < 4; i++)
#pragma unroll
        for (int j = 0; j < 4; j++)
#pragma unroll
            for (int q = 0; q < 4; q++) acc[i][j][q] = 0.0f;

    // prologue: chunk 0 -> buf 0
#pragma unroll
    for (int j = 0; j < 4; j++) {
        cp16(sA0 + dstoff + 16 * j, asrc + 8 * j);
        cp16(sB0 + dstoff + 16 * j, bsrc + 8 * j);
    }
    cp_commit();

    const int nIter = KP / 64;   // 48
    for (int it = 0; it < nIter; ++it) {
        const int s = it & 1;
        __syncthreads();   // all warps done reading buf s (prev round)

        if (it + 1 < nIter) {
            const int k0 = (it + 1) * 64;
            const u32 d = ((it + 1) & 1) * bufstride;
#pragma unroll
            for (int j = 0; j < 4; j++) {
                cp16(sA0 + d + dstoff + 16 * j, asrc + k0 + 8 * j);
                cp16(sB0 + d + dstoff + 16 * j, bsrc + k0 + 8 * j);
            }
            cp_commit();
            cp_wait1();
        } else {
            cp_wait0();
        }
        __syncthreads();   // buf s visible

        const u32 sA = sA0 + s * bufstride;
        const u32 sB = sB0 + s * bufstride;
#pragma unroll
        for (int ks = 0; ks < 4; ks++) {
            u32 af[4][4], bf[2][4];
#pragma unroll
            for (int mt = 0; mt < 4; mt++)
                ldsm4(af[mt], sA + (wm * 64 + mt * 16) * GLD + aoff + ks * 32);
#pragma unroll
            for (int np = 0; np < 2; np++)
                ldsm4(bf[np], sB + (wn * 32 + np * 16) * GLD + boff + ks * 32);
#pragma unroll
            for (int mt = 0; mt < 4; mt++) {
#pragma unroll
                for (int nt = 0; nt < 4; nt++)
                    mma16816(acc[mt][nt], af[mt], bf[nt >> 1] + (nt & 1) * 2);
            }
        }
    }

    // epilogue: add bias, store fp32
#pragma unroll
    for (int mt = 0; mt < 4; mt++) {
        int row0 = m0 + wm * 64 + mt * 16 + (lane >> 2);
#pragma unroll
        for (int half_m = 0; half_m < 2; half_m++) {
            int row = row0 + half_m * 8;
            int cb = row / cRPB;
            float* crow = C + (long long)cb * cBS + (long long)(row - cb * cRPB) * N;
#pragma unroll
            for (int nt = 0; nt < 4; nt++) {
                int col = n0 + wn * 32 + nt * 8 + 2 * (lane & 3);
                float2 b2 = *(const float2*)(bias + col);
                float2 o = make_float2(acc[mt][nt][2 * half_m] + b2.x,
                                       acc[mt][nt][2 * half_m + 1] + b2.y);
                *(float2*)(crow + col) = o;
            }
        }
    }
}

// ---------------------------------------------------------------------------
// Split QKV + RMSNorm + RoPE -> bf16 hi/lo operand buffers.
// One warp per (b, n, head); Q pre-scaled by softmax scale 1/8.
// ---------------------------------------------------------------------------
__global__ void __launch_bounds__(256)
qkv_post(const float* __restrict__ qs1, const float* __restrict__ ks1,
         const float* __restrict__ qs2, const float* __restrict__ ks2)
{
    int w = (blockIdx.x * blockDim.x + threadIdx.x) >> 5;
    int lane = threadIdx.x & 31;
    int h = w & 15;
    int n = (w >> 4) & (NT - 1);
    int b = w >> 15;

    const float* row = g_qkv + (long long)(b * NT + n) * (3 * DM);
    const float* qs = (n < NSEG1) ? qs1 : qs2;
    const float* ks = (n < NSEG1) ? ks1 : ks2;

    float pos = (float)n;
    float e = (float)(2 * lane) * (1.0f / 64.0f);
    float invf = expf(-e * 9.210340371976184f);
    float ang = pos * invf;
    float cs = cosf(ang), sn = sinf(ang);

    long long obase = ((long long)(b * NH + h) * NT + n) * HD + 2 * lane;
    int doff = h * HD + 2 * lane;

    // Q (scaled 1/8)
    {
        float2 v = *(const float2*)(row + doff);
        float ss = v.x * v.x + v.y * v.y;
#pragma unroll
        for (int off = 16; off; off >>= 1) ss += __shfl_xor_sync(0xffffffffu, ss, off);
        float inv = rsqrtf(ss * (1.0f / 64.0f) + 1e-6f);
        float a = v.x * inv * qs[2 * lane];
        float c = v.y * inv * qs[2 * lane + 1];
        float ox = (a * cs - c * sn) * 0.125f;
        float oy = (a * sn + c * cs) * 0.125f;
        u32 hp, lp;
        split_pack(ox, oy, hp, lp);
        *(u32*)(g_qh + obase) = hp;
        *(u32*)(g_ql + obase) = lp;
    }
    // K
    {
        float2 v = *(const float2*)(row + DM + doff);
        float ss = v.x * v.x + v.y * v.y;
#pragma unroll
        for (int off = 16; off; off >>= 1) ss += __shfl_xor_sync(0xffffffffu, ss, off);
        float inv = rsqrtf(ss * (1.0f / 64.0f) + 1e-6f);
        float a = v.x * inv * ks[2 * lane];
        float c = v.y * inv * ks[2 * lane + 1];
        float ox = a * cs - c * sn;
        float oy = a * sn + c * cs;
        u32 hp, lp;
        split_pack(ox, oy, hp, lp);
        *(u32*)(g_kh + obase) = hp;
        *(u32*)(g_kl + obase) = lp;
    }
    // V
    {
        float2 v = *(const float2*)(row + 2 * DM + doff);
        u32 hp, lp;
        split_pack(v.x, v.y, hp, lp);
        *(u32*)(g_vh + obase) = hp;
        *(u32*)(g_vl + obase) = lp;
    }
}

// ---------------------------------------------------------------------------
// Flash attention on the tensor pipe (round-10 verified), epilogue now writes
// the [hi|hi|lo] split x2 buffer directly (no fp32 x + cvt round-trip).
// ---------------------------------------------------------------------------
#define FTILE 18432                    // 128 rows x 144 B
#define FSQH  0
#define FSQL  FTILE
#define FSKV  (2 * FTILE)
#define FBUF  (4 * FTILE)
#define FA_SMEM (FSKV + 2 * FBUF)      // 184320 B

__global__ void __launch_bounds__(256, 1)
flash_attn()
{
    extern __shared__ char smx[];
    const u32 sbase = (u32)__cvta_generic_to_shared(smx);
    const int b = blockIdx.z, h = blockIdx.y;
    const int q0 = blockIdx.x * 128;
    const int tid = threadIdx.x;
    const int w = tid >> 5;
    const int lane = tid & 31;

    const long long bh = (long long)(b * NH + h) * NT;

    const int r = tid >> 1;
    const int hf = tid & 1;
    const u32 ldst = r * 144 + hf * 64;
    const __nv_bfloat16* qh_s = g_qh + (bh + q0 + r) * HD + hf * 32;
    const __nv_bfloat16* ql_s = g_ql + (bh + q0 + r) * HD + hf * 32;
    const __nv_bfloat16* kh_s = g_kh + (bh + r) * HD + hf * 32;
    const __nv_bfloat16* kl_s = g_kl + (bh + r) * HD + hf * 32;
    const __nv_bfloat16* vh_s = g_vh + (bh + r) * HD + hf * 32;
    const __nv_bfloat16* vl_s = g_vl + (bh + r) * HD + hf * 32;

#pragma unroll
    for (int j = 0; j < 4; j++) {
        cp16(sbase + FSQH + ldst + 16 * j, qh_s + 8 * j);
        cp16(sbase + FSQL + ldst + 16 * j, ql_s + 8 * j);
    }
    cp_commit();
#pragma unroll
    for (int j = 0; j < 4; j++) {
        cp16(sbase + FSKV + 0 * FTILE + ldst + 16 * j, kh_s + 8 * j);
        cp16(sbase + FSKV + 1 * FTILE + ldst + 16 * j, kl_s + 8 * j);
        cp16(sbase + FSKV + 2 * FTILE + ldst + 16 * j, vh_s + 8 * j);
        cp16(sbase + FSKV + 3 * FTILE + ldst + 16 * j, vl_s + 8 * j);
    }
    cp_commit();

    const u32 aoff = (lane & 15) * 144 + (lane >> 4) * 16;
    const u32 boff = ((lane & 7) + ((lane >> 4) << 3)) * 144 + ((lane >> 3) & 1) * 16;
    const u32 voff = ((lane & 7) + ((lane >> 3) & 1) * 8) * 144 + (lane >> 4) * 16;

    u32 qfh[4][4], qfl[4][4];
    float o[8][4];
    float m0 = -1e30f, m1 = -1e30f, l0 = 0.0f, l1 = 0.0f;
#pragma unroll
    for (int i = 0; i < 8; i++)
#pragma unroll
        for (int q = 0; q < 4; q++) o[i][q] = 0.0f;

    const int nTiles = NT / 128;
    for (int t = 0; t < nTiles; ++t) {
        const int s = t & 1;

        if (t + 1 < nTiles) {
            const long long roff = (long long)(t + 1) * 128 * HD;
            const u32 dbuf = sbase + FSKV + ((t + 1) & 1) * FBUF;
#pragma unroll
            for (int j = 0; j < 4; j++) {
                cp16(dbuf + 0 * FTILE + ldst + 16 * j, kh_s + roff + 8 * j);
                cp16(dbuf + 1 * FTILE + ldst + 16 * j, kl_s + roff + 8 * j);
                cp16(dbuf + 2 * FTILE + ldst + 16 * j, vh_s + roff + 8 * j);
                cp16(dbuf + 3 * FTILE + ldst + 16 * j, vl_s + roff + 8 * j);
            }
            cp_commit();
            cp_wait1();
        } else {
            cp_wait0();
        }
        __syncthreads();

        if (t == 0) {
            const u32 qbh = sbase + FSQH + w * 16 * 144;
            const u32 qbl = sbase + FSQL + w * 16 * 144;
#pragma unroll
            for (int kc = 0; kc < 4; kc++) {
                ldsm4(qfh[kc], qbh + kc * 32 + aoff);
                ldsm4(qfl[kc], qbl + kc * 32 + aoff);
            }
        }

        const u32 skh = sbase + FSKV + s * FBUF;
        const u32 skl = skh + FTILE;
        const u32 svh = skh + 2 * FTILE;
        const u32 svl = skh + 3 * FTILE;

        // ---- S = Q K^T ----
        float sc[16][4];
#pragma unroll
        for (int nt = 0; nt < 16; nt++)
#pragma unroll
            for (int q = 0; q < 4; q++) sc[nt][q] = 0.0f;

#pragma unroll
        for (int np = 0; np < 8; np++) {
#pragma unroll
            for (int kc = 0; kc < 4; kc++) {
                u32 bh4[4], bl4[4];
                ldsm4(bh4, skh + np * 16 * 144 + kc * 32 + boff);
                ldsm4(bl4, skl + np * 16 * 144 + kc * 32 + boff);
                mma16816(sc[2 * np],     qfh[kc], bh4);
                mma16816(sc[2 * np],     qfl[kc], bh4);
                mma16816(sc[2 * np],     qfh[kc], bl4);
                mma16816(sc[2 * np + 1], qfh[kc], bh4 + 2);
                mma16816(sc[2 * np + 1], qfl[kc], bh4 + 2);
                mma16816(sc[2 * np + 1], qfh[kc], bl4 + 2);
            }
        }

        // ---- online softmax ----
        float mt0 = sc[0][0], mt1 = sc[0][2];
#pragma unroll
        for (int nt = 0; nt < 16; nt++) {
            mt0 = fmaxf(mt0, fmaxf(sc[nt][0], sc[nt][1]));
            mt1 = fmaxf(mt1, fmaxf(sc[nt][2], sc[nt][3]));
        }
        mt0 = fmaxf(mt0, __shfl_xor_sync(0xffffffffu, mt0, 1));
        mt0 = fmaxf(mt0, __shfl_xor_sync(0xffffffffu, mt0, 2));
        mt1 = fmaxf(mt1, __shfl_xor_sync(0xffffffffu, mt1, 1));
        mt1 = fmaxf(mt1, __shfl_xor_sync(0xffffffffu, mt1, 2));
        float nm0 = fmaxf(m0, mt0), nm1 = fmaxf(m1, mt1);
        float f0 = fexp(m0 - nm0), f1 = fexp(m1 - nm1);
        m0 = nm0; m1 = nm1;

        float ts0 = 0.0f, ts1 = 0.0f;
#pragma unroll
        for (int nt = 0; nt < 16; nt++) {
            sc[nt][0] = fexp(sc[nt][0] - nm0);
            sc[nt][1] = fexp(sc[nt][1] - nm0);
            sc[nt][2] = fexp(sc[nt][2] - nm1);
            sc[nt][3] = fexp(sc[nt][3] - nm1);
            ts0 += sc[nt][0] + sc[nt][1];
            ts1 += sc[nt][2] + sc[nt][3];
        }
        ts0 += __shfl_xor_sync(0xffffffffu, ts0, 1);
        ts0 += __shfl_xor_sync(0xffffffffu, ts0, 2);
        ts1 += __shfl_xor_sync(0xffffffffu, ts1, 1);
        ts1 += __shfl_xor_sync(0xffffffffu, ts1, 2);
        l0 = l0 * f0 + ts0;
        l1 = l1 * f1 + ts1;

#pragma unroll
        for (int nt = 0; nt < 8; nt++) {
            o[nt][0] *= f0; o[nt][1] *= f0;
            o[nt][2] *= f1; o[nt][3] *= f1;
        }

        // ---- O += P V ----
#pragma unroll
        for (int kc = 0; kc < 8; kc++) {
            u32 ah[4], al[4];
            split_pack(sc[2 * kc][0],     sc[2 * kc][1],     ah[0], al[0]);
            split_pack(sc[2 * kc][2],     sc[2 * kc][3],     ah[1], al[1]);
            split_pack(sc[2 * kc + 1][0], sc[2 * kc + 1][1], ah[2], al[2]);
            split_pack(sc[2 * kc + 1][2], sc[2 * kc + 1][3], ah[3], al[3]);
#pragma unroll
            for (int vp = 0; vp < 4; vp++) {
                u32 vh4[4], vl4[4];
                ldsm4t(vh4, svh + kc * 16 * 144 + vp * 32 + voff);
                ldsm4t(vl4, svl + kc * 16 * 144 + vp * 32 + voff);
                mma16816(o[2 * vp],     ah, vh4);
                mma16816(o[2 * vp],     al, vh4);
                mma16816(o[2 * vp],     ah, vl4);
                mma16816(o[2 * vp + 1], ah, vh4 + 2);
                mma16816(o[2 * vp + 1], al, vh4 + 2);
                mma16816(o[2 * vp + 1], ah, vl4 + 2);
            }
        }
        __syncthreads();
    }

    // ---- finalize: write split [hi|hi|lo] x2 buffer directly ----
    float inv0 = 1.0f / l0, inv1 = 1.0f / l1;
    int r0g = q0 + w * 16 + (lane >> 2);
    long long row0 = (long long)b * NT + r0g;
    __nv_bfloat16* p0 = g_x2 + row0 * KP;
    __nv_bfloat16* p1 = g_x2 + (row0 + 8) * KP;
    int cbase = h * HD + 2 * (lane & 3);
#pragma unroll
    for (int nt = 0; nt < 8; nt++) {
        int c = cbase + 8 * nt;
        u32 hp, lp;
        split_pack(o[nt][0] * inv0, o[nt][1] * inv0, hp, lp);
        *(u32*)(p0 + c) = hp;
        *(u32*)(p0 + 1024 + c) = hp;
        *(u32*)(p0 + 2048 + c) = lp;
        split_pack(o[nt][2] * inv1, o[nt][3] * inv1, hp, lp);
        *(u32*)(p1 + c) = hp;
        *(u32*)(p1 + 1024 + c) = hp;
        *(u32*)(p1 + 2048 + c) = lp;
    }
}

// ---------------------------------------------------------------------------
// Launch
// ---------------------------------------------------------------------------
extern "C" void kernel_launch(void* const* d_in, const int* in_sizes, int n_in,
                              void* d_out, int out_size)
{
    const float* x1  = (const float*)d_in[0];
    const float* x2  = (const float*)d_in[1];
    const float* Wq1 = (const float*)d_in[2];
    const float* bq1 = (const float*)d_in[3];
    const float* Wq2 = (const float*)d_in[4];
    const float* bq2 = (const float*)d_in[5];
    const float* Wo1 = (const float*)d_in[6];
    const float* bo1 = (const float*)d_in[7];
    const float* Wo2 = (const float*)d_in[8];
    const float* bo2 = (const float*)d_in[9];
    const float* qs1 = (const float*)d_in[10];
    const float* ks1 = (const float*)d_in[11];
    const float* qs2 = (const float*)d_in[12];
    const float* ks2 = (const float*)d_in[13];
    float* out = (float*)d_out;

    float* qkv;
    cudaGetSymbolAddress((void**)&qkv, g_qkv);
    __nv_bfloat16 *a1, *a2, *x2b, *w1, *w2, *o1, *o2;
    cudaGetSymbolAddress((void**)&a1, g_a1);
    cudaGetSymbolAddress((void**)&a2, g_a2);
    cudaGetSymbolAddress((void**)&x2b, g_x2);
    cudaGetSymbolAddress((void**)&w1, g_w1);
    cudaGetSymbolAddress((void**)&w2, g_w2);
    cudaGetSymbolAddress((void**)&o1, g_o1);
    cudaGetSymbolAddress((void**)&o2, g_o2);

    cudaFuncSetAttribute(flash_attn, cudaFuncAttributeMaxDynamicSharedMemorySize,
                         FA_SMEM);
    cudaFuncSetAttribute(gemm_mma2, cudaFuncAttributeMaxDynamicSharedMemorySize,
                         GSMEM);

    // --- bf16 split conversions (A: hi|hi|lo, B: hi|lo|hi) ---
    cvt_split<<<1024, 256>>>((const float4*)x1,  a1, 3072 * 1024 / 4, 0);
    cvt_split<<<1024, 256>>>((const float4*)x2,  a2, 1024 * 1024 / 4, 0);
    cvt_split<<<1024, 256>>>((const float4*)Wq1, w1, 3072 * 1024 / 4, 1);
    cvt_split<<<1024, 256>>>((const float4*)Wq2, w2, 3072 * 1024 / 4, 1);
    cvt_split<<<1024, 256>>>((const float4*)Wo1, o1, 1024 * 1024 / 4, 1);
    cvt_split<<<1024, 256>>>((const float4*)Wo2, o2, 1024 * 1024 / 4, 1);

    // --- QKV projections, both segments in ONE launch ---
    gemm_mma2<<<dim3(24, 32), 256, GSMEM>>>(
        a1, w1, bq1, qkv,
        3072, 3072, NSEG1, (long long)NT * 3 * DM,
        a2, w2, bq2, qkv + (long long)NSEG1 * 3 * DM,
        1024, 1024, NSEG2, (long long)NT * 3 * DM,
        3072, 24);

    // --- split + RMSNorm + RoPE -> bf16 hi/lo operands ---
    qkv_post<<<(BATCH * NT * NH) / 8, 256>>>(qs1, ks1, qs2, ks2);

    // --- attention (tensor pipe), writes split x2 buffer directly ---
    flash_attn<<<dim3(NT / 128, NH, BATCH), 256, FA_SMEM>>>();

    // --- output projections, both segments in ONE launch ---
    gemm_mma2<<<dim3(8, 32), 256, GSMEM>>>(
        x2b, o1, bo1, out,
        1536, 2048, NSEG1, (long long)NSEG1 * DM,
        x2b + (long long)NSEG1 * KP, o2, bo2, out + (long long)BATCH * NSEG1 * DM,
        512, 2048, NSEG2, (long long)NSEG2 * DM,
        1024, 24);
}